// round 1
// baseline (speedup 1.0000x reference)
#include <cuda_runtime.h>
#include <math.h>

// Problem constants
#define Bb   8
#define Ss   1024
#define Ee   512
#define Hh   8
#define DHd  64
#define Mm   (Bb * Ss)        // 8192 rows
#define QKVN (3 * Ee)         // 1536
#define LOCALW 3

// ---------------- scratch (device globals; no allocations allowed) ---------
__device__ float g_qkv_l[(size_t)Mm * QKVN];   // [8192][1536] q|k|v local block
__device__ float g_qkv_g[(size_t)Mm * QKVN];   // [8192][1536] q|k|v global block
__device__ float g_attn[(size_t)Mm * 2 * Ee];  // [8192][1024] cols 0:512 local, 512:1024 global
__device__ float g_Wc[(size_t)Ee * 2 * Ee];    // [512][1024] combined (Wf_l@Wl_out | Wf_g@Wg_out)
__device__ float g_bc[Ee];                     // combined bias

// ---------------- generic tiled fp32 GEMM ----------------------------------
// TRANSB=true : C[m][n] = sum_k A[m][k] * W[n][k]   (W is [N,K] row-major)
// TRANSB=false: C[m][n] = sum_k A[m][k] * W[k][n]   (W is [K,N] row-major)
// Requires M%64==0, N%64==0, K%16==0.
#define BM 64
#define BN 64
#define BK 16
#define SPITCH 68

template<bool TRANSB, bool RELU, bool BIAS>
__global__ __launch_bounds__(256)
void gemm_kernel(const float* __restrict__ A, int lda,
                 const float* __restrict__ W, int ldb,
                 const float* __restrict__ bias,
                 float* __restrict__ C, int ldc, int K)
{
    __shared__ float As[BK][SPITCH];
    __shared__ float Bs[BK][SPITCH];
    const int t  = threadIdx.x;
    const int tx = t & 15, ty = t >> 4;
    const int m0 = blockIdx.y * BM, n0 = blockIdx.x * BN;
    const int lr = t >> 2;            // 0..63
    const int lk = (t & 3) << 2;      // 0,4,8,12
    float acc[4][4] = {};

    for (int k0 = 0; k0 < K; k0 += BK) {
        // A tile, transposed into As[k][m]
        {
            float4 v = *(const float4*)(A + (size_t)(m0 + lr) * lda + k0 + lk);
            As[lk + 0][lr] = v.x; As[lk + 1][lr] = v.y;
            As[lk + 2][lr] = v.z; As[lk + 3][lr] = v.w;
        }
        if (TRANSB) {
            float4 v = *(const float4*)(W + (size_t)(n0 + lr) * ldb + k0 + lk);
            Bs[lk + 0][lr] = v.x; Bs[lk + 1][lr] = v.y;
            Bs[lk + 2][lr] = v.z; Bs[lk + 3][lr] = v.w;
        } else {
            const int kk = t >> 4, c = (t & 15) << 2;
            *(float4*)&Bs[kk][c] =
                *(const float4*)(W + (size_t)(k0 + kk) * ldb + n0 + c);
        }
        __syncthreads();
        #pragma unroll
        for (int kk = 0; kk < BK; kk++) {
            float4 a = *(const float4*)&As[kk][ty << 2];
            float4 b = *(const float4*)&Bs[kk][tx << 2];
            float av[4] = {a.x, a.y, a.z, a.w};
            float bv[4] = {b.x, b.y, b.z, b.w};
            #pragma unroll
            for (int i = 0; i < 4; i++)
                #pragma unroll
                for (int j = 0; j < 4; j++)
                    acc[i][j] = fmaf(av[i], bv[j], acc[i][j]);
        }
        __syncthreads();
    }

    float bj[4] = {0.f, 0.f, 0.f, 0.f};
    if (BIAS) {
        float4 bb = *(const float4*)(bias + n0 + (tx << 2));
        bj[0] = bb.x; bj[1] = bb.y; bj[2] = bb.z; bj[3] = bb.w;
    }
    #pragma unroll
    for (int i = 0; i < 4; i++) {
        float v0 = acc[i][0] + bj[0];
        float v1 = acc[i][1] + bj[1];
        float v2 = acc[i][2] + bj[2];
        float v3 = acc[i][3] + bj[3];
        if (RELU) {
            v0 = fmaxf(v0, 0.f); v1 = fmaxf(v1, 0.f);
            v2 = fmaxf(v2, 0.f); v3 = fmaxf(v3, 0.f);
        }
        *(float4*)(C + (size_t)(m0 + (ty << 2) + i) * ldc + n0 + (tx << 2)) =
            make_float4(v0, v1, v2, v3);
    }
}

// ---------------- combined bias: b_c = bf + Wf_l@bl_out + Wf_g@bg_out ------
__global__ void bias_combine_kernel(const float* __restrict__ Wf,
                                    const float* __restrict__ bl,
                                    const float* __restrict__ bg,
                                    const float* __restrict__ bf)
{
    int o = blockIdx.x * blockDim.x + threadIdx.x;
    if (o >= Ee) return;
    float acc = bf[o];
    const float* row = Wf + (size_t)o * (2 * Ee);
    for (int j = 0; j < Ee; j++)
        acc += row[j] * bl[j] + row[Ee + j] * bg[j];
    g_bc[o] = acc;
}

// ---------------- local (banded, window +-3) attention ---------------------
// One warp per (b,h,q). Writes g_attn[:, 0:512].
__global__ __launch_bounds__(256)
void local_attn_kernel(const float* __restrict__ qkv)
{
    const int warp = (blockIdx.x * blockDim.x + threadIdx.x) >> 5;
    const int lane = threadIdx.x & 31;
    const int q  = warp & (Ss - 1);
    const int bh = warp >> 10;          // 0..63
    const int b  = bh >> 3, h = bh & 7;

    const float* base = qkv + (size_t)(b * Ss) * QKVN + h * DHd;
    const float* qrow = base + (size_t)q * QKVN;
    const float q0 = qrow[lane], q1 = qrow[lane + 32];

    float s[7];
    float mmax = -1e30f;
    #pragma unroll
    for (int jj = 0; jj < 7; jj++) {
        const int j = q - LOCALW + jj;
        const bool valid = (j >= 0) && (j < Ss);
        float d = 0.f;
        if (valid) {
            const float* krow = base + (size_t)j * QKVN + Ee;
            d = q0 * krow[lane] + q1 * krow[lane + 32];
        }
        #pragma unroll
        for (int off = 16; off; off >>= 1)
            d += __shfl_xor_sync(0xffffffffu, d, off);
        d = valid ? d * 0.125f : -1e30f;
        s[jj] = d;
        mmax = fmaxf(mmax, d);
    }
    float sum = 0.f;
    #pragma unroll
    for (int jj = 0; jj < 7; jj++) {
        s[jj] = __expf(s[jj] - mmax);
        sum += s[jj];
    }
    const float inv = 1.f / sum;
    float o0 = 0.f, o1 = 0.f;
    #pragma unroll
    for (int jj = 0; jj < 7; jj++) {
        const int j = q - LOCALW + jj;
        if (j >= 0 && j < Ss) {
            const float* vrow = base + (size_t)j * QKVN + 2 * Ee;
            o0 = fmaf(s[jj], vrow[lane],      o0);
            o1 = fmaf(s[jj], vrow[lane + 32], o1);
        }
    }
    float* out = g_attn + (size_t)(b * Ss + q) * (2 * Ee) + h * DHd;
    out[lane]      = o0 * inv;
    out[lane + 32] = o1 * inv;
}

// ---------------- global (full) attention, flash-style ---------------------
// grid (S/64, B*H), 256 threads, dynamic smem. Writes g_attn[:, 512:1024].
#define FP 68
#define FSMEM (4 * 64 * FP * (int)sizeof(float))   // 69632 B

__global__ __launch_bounds__(256)
void global_attn_kernel(const float* __restrict__ qkv)
{
    extern __shared__ float sm[];
    float* QsT = sm;                 // [d][q]  64 x FP
    float* KsT = sm + 64 * FP;       // [d][k]
    float* Vs  = sm + 2 * 64 * FP;   // [k][d]
    float* Ps  = sm + 3 * 64 * FP;   // [q][k]

    const int t  = threadIdx.x;
    const int tx = t & 15, ty = t >> 4;
    const int bh = blockIdx.y;
    const int b  = bh >> 3, h = bh & 7;
    const int q0 = blockIdx.x << 6;
    const float* base = qkv + (size_t)(b * Ss) * QKVN + h * DHd;

    // Q tile, transposed + pre-scaled by 1/sqrt(dh)
    #pragma unroll
    for (int u = 0; u < 4; u++) {
        const int idx = t + (u << 8);
        const int r = idx >> 4;
        const int c = (idx & 15) << 2;
        float4 v = *(const float4*)(base + (size_t)(q0 + r) * QKVN + c);
        QsT[(c + 0) * FP + r] = v.x * 0.125f;
        QsT[(c + 1) * FP + r] = v.y * 0.125f;
        QsT[(c + 2) * FP + r] = v.z * 0.125f;
        QsT[(c + 3) * FP + r] = v.w * 0.125f;
    }

    float o[4][4] = {};
    float mi[4] = {-INFINITY, -INFINITY, -INFINITY, -INFINITY};
    float li[4] = {0.f, 0.f, 0.f, 0.f};

    for (int kt = 0; kt < Ss; kt += 64) {
        // K tile (transposed) and V tile (natural)
        #pragma unroll
        for (int u = 0; u < 4; u++) {
            const int idx = t + (u << 8);
            const int r = idx >> 4;
            const int c = (idx & 15) << 2;
            float4 vk = *(const float4*)(base + (size_t)(kt + r) * QKVN + Ee + c);
            KsT[(c + 0) * FP + r] = vk.x;
            KsT[(c + 1) * FP + r] = vk.y;
            KsT[(c + 2) * FP + r] = vk.z;
            KsT[(c + 3) * FP + r] = vk.w;
            float4 vv = *(const float4*)(base + (size_t)(kt + r) * QKVN + 2 * Ee + c);
            *(float4*)(Vs + r * FP + c) = vv;
        }
        __syncthreads();

        // S = Q @ K^T  (reduction over d)
        float s[4][4] = {};
        #pragma unroll 16
        for (int kk = 0; kk < 64; kk++) {
            float4 a = *(const float4*)(QsT + kk * FP + (ty << 2));
            float4 bq = *(const float4*)(KsT + kk * FP + (tx << 2));
            float av[4] = {a.x, a.y, a.z, a.w};
            float bv[4] = {bq.x, bq.y, bq.z, bq.w};
            #pragma unroll
            for (int i = 0; i < 4; i++)
                #pragma unroll
                for (int j = 0; j < 4; j++)
                    s[i][j] = fmaf(av[i], bv[j], s[i][j]);
        }

        // online softmax (row reductions across the 16 tx lanes)
        #pragma unroll
        for (int i = 0; i < 4; i++) {
            float rm = fmaxf(fmaxf(s[i][0], s[i][1]), fmaxf(s[i][2], s[i][3]));
            #pragma unroll
            for (int off = 8; off; off >>= 1)
                rm = fmaxf(rm, __shfl_xor_sync(0xffffffffu, rm, off));
            const float mnew = fmaxf(mi[i], rm);
            const float sc = __expf(mi[i] - mnew);
            mi[i] = mnew;
            float rs = 0.f;
            #pragma unroll
            for (int j = 0; j < 4; j++) {
                s[i][j] = __expf(s[i][j] - mnew);
                rs += s[i][j];
            }
            #pragma unroll
            for (int off = 8; off; off >>= 1)
                rs += __shfl_xor_sync(0xffffffffu, rs, off);
            li[i] = li[i] * sc + rs;
            #pragma unroll
            for (int j = 0; j < 4; j++) o[i][j] *= sc;
            *(float4*)(Ps + ((ty << 2) + i) * FP + (tx << 2)) =
                make_float4(s[i][0], s[i][1], s[i][2], s[i][3]);
        }
        __syncthreads();

        // O += P @ V
        #pragma unroll 16
        for (int kk = 0; kk < 64; kk++) {
            float av[4];
            #pragma unroll
            for (int i = 0; i < 4; i++)
                av[i] = Ps[((ty << 2) + i) * FP + kk];
            float4 bv4 = *(const float4*)(Vs + kk * FP + (tx << 2));
            float bv[4] = {bv4.x, bv4.y, bv4.z, bv4.w};
            #pragma unroll
            for (int i = 0; i < 4; i++)
                #pragma unroll
                for (int j = 0; j < 4; j++)
                    o[i][j] = fmaf(av[i], bv[j], o[i][j]);
        }
        __syncthreads();
    }

    #pragma unroll
    for (int i = 0; i < 4; i++) {
        const float inv = 1.f / li[i];
        *(float4*)(g_attn + (size_t)(b * Ss + q0 + (ty << 2) + i) * (2 * Ee)
                   + Ee + h * DHd + (tx << 2)) =
            make_float4(o[i][0] * inv, o[i][1] * inv, o[i][2] * inv, o[i][3] * inv);
    }
}

// ---------------- launcher --------------------------------------------------
extern "C" void kernel_launch(void* const* d_in, const int* in_sizes, int n_in,
                              void* d_out, int out_size)
{
    (void)in_sizes; (void)n_in; (void)out_size;
    const float* x      = (const float*)d_in[0];
    const float* Wl_in  = (const float*)d_in[1];
    const float* bl_in  = (const float*)d_in[2];
    const float* Wl_out = (const float*)d_in[3];
    const float* bl_out = (const float*)d_in[4];
    const float* Wg_in  = (const float*)d_in[5];
    const float* bg_in  = (const float*)d_in[6];
    const float* Wg_out = (const float*)d_in[7];
    const float* bg_out = (const float*)d_in[8];
    const float* Wf     = (const float*)d_in[9];
    const float* bf     = (const float*)d_in[10];
    float* out = (float*)d_out;

    float *qkv_l, *qkv_g, *attn, *Wc, *bc;
    cudaGetSymbolAddress((void**)&qkv_l, g_qkv_l);
    cudaGetSymbolAddress((void**)&qkv_g, g_qkv_g);
    cudaGetSymbolAddress((void**)&attn,  g_attn);
    cudaGetSymbolAddress((void**)&Wc,    g_Wc);
    cudaGetSymbolAddress((void**)&bc,    g_bc);

    cudaFuncSetAttribute(global_attn_kernel,
                         cudaFuncAttributeMaxDynamicSharedMemorySize, FSMEM);

    const dim3 thr(256);

    // 1) QKV projections for both attention blocks
    gemm_kernel<true, false, true><<<dim3(QKVN / BN, Mm / BM), thr>>>(
        x, Ee, Wl_in, Ee, bl_in, qkv_l, QKVN, Ee);
    gemm_kernel<true, false, true><<<dim3(QKVN / BN, Mm / BM), thr>>>(
        x, Ee, Wg_in, Ee, bg_in, qkv_g, QKVN, Ee);

    // 2) Combined epilogue weights: Wc = [Wf_l @ Wl_out | Wf_g @ Wg_out]
    gemm_kernel<false, false, false><<<dim3(Ee / BN, Ee / BM), thr>>>(
        Wf, 2 * Ee, Wl_out, Ee, nullptr, Wc, 2 * Ee, Ee);
    gemm_kernel<false, false, false><<<dim3(Ee / BN, Ee / BM), thr>>>(
        Wf + Ee, 2 * Ee, Wg_out, Ee, nullptr, Wc + Ee, 2 * Ee, Ee);
    bias_combine_kernel<<<2, 256>>>(Wf, bl_out, bg_out, bf);

    // 3) Attention
    local_attn_kernel<<<(Bb * Hh * Ss) / 8, 256>>>(qkv_l);
    global_attn_kernel<<<dim3(Ss / 64, Bb * Hh), 256, FSMEM>>>(qkv_g);

    // 4) Fused final projection + ReLU
    gemm_kernel<true, true, true><<<dim3(Ee / BN, Mm / BM), thr>>>(
        attn, 2 * Ee, Wc, 2 * Ee, bc, out, Ee, 2 * Ee);
}

// round 3
// speedup vs baseline: 1.6916x; 1.6916x over previous
#include <cuda_runtime.h>
#include <cuda_bf16.h>
#include <math.h>
#include <stdint.h>

// Problem constants
#define Bb   8
#define Ss   1024
#define Ee   512
#define Hh   8
#define DHd  64
#define Mm   (Bb * Ss)        // 8192
#define QKVN (3 * Ee)         // 1536
#define LOCALW 3

// ---------------- scratch (device globals) ----------------------------------
__device__ float g_qkv_l[(size_t)Mm * QKVN];
__device__ float g_qkv_g[(size_t)Mm * QKVN];
__device__ float g_attn [(size_t)Mm * 2 * Ee];
__device__ float g_Wc   [(size_t)Ee * 2 * Ee];
__device__ float g_bc   [Ee];
__device__ __nv_bfloat16 g_A1 [(size_t)Mm * 3 * Ee];        // x split    [8192,1536]
__device__ __nv_bfloat16 g_B1l[(size_t)QKVN * 3 * Ee];      // Wl_in split [1536,1536]
__device__ __nv_bfloat16 g_B1g[(size_t)QKVN * 3 * Ee];      // Wg_in split
__device__ __nv_bfloat16 g_A2 [(size_t)Mm * 3 * 2 * Ee];    // attn split [8192,3072]
__device__ __nv_bfloat16 g_B2 [(size_t)Ee * 3 * 2 * Ee];    // Wc split   [512,3072]

// ---------------- PTX helpers (base ISA only — no tcgen05!) -----------------
__device__ __forceinline__ uint32_t smem_u32(const void* p) {
    uint32_t a;
    asm("{ .reg .u64 t; cvta.to.shared.u64 t, %1; cvt.u32.u64 %0, t; }"
        : "=r"(a) : "l"(p));
    return a;
}
__device__ __forceinline__ uint32_t sw128(uint32_t o) { return o ^ ((o >> 3) & 0x70); }

__device__ __forceinline__ void cp16(uint32_t dst, const void* src) {
    asm volatile("cp.async.cg.shared.global [%0], [%1], 16;"
                 :: "r"(dst), "l"(src) : "memory");
}
__device__ __forceinline__ void ldsm4(uint32_t* d, uint32_t a) {
    asm volatile("ldmatrix.sync.aligned.m8n8.x4.shared.b16 {%0,%1,%2,%3}, [%4];"
                 : "=r"(d[0]), "=r"(d[1]), "=r"(d[2]), "=r"(d[3]) : "r"(a));
}
__device__ __forceinline__ void mma16816(float* c, const uint32_t* a,
                                         uint32_t b0, uint32_t b1) {
    asm volatile("mma.sync.aligned.m16n8k16.row.col.f32.bf16.bf16.f32 "
                 "{%0,%1,%2,%3}, {%4,%5,%6,%7}, {%8,%9}, {%0,%1,%2,%3};"
                 : "+f"(c[0]), "+f"(c[1]), "+f"(c[2]), "+f"(c[3])
                 : "r"(a[0]), "r"(a[1]), "r"(a[2]), "r"(a[3]), "r"(b0), "r"(b1));
}

// ---------------- mma.sync bf16 GEMM: C = A @ B^T (+bias, opt relu) ---------
// A: [M,K] bf16 row-major; B: [N,K] bf16 row-major; C: [M,ldc] fp32.
// CTA tile 128x128, K chunk 64 (=128 bytes/row, SW128), cp.async double buffer.
// 8 warps: warp_m = w&3 (32 rows), warp_n = w>>2 (64 cols).
#define MMA_SMEM 65536

template<bool RELU>
__global__ void __launch_bounds__(256)
mma_gemm(const __nv_bfloat16* __restrict__ A, const __nv_bfloat16* __restrict__ B,
         const float* __restrict__ bias, float* __restrict__ C, int K, int ldc)
{
    extern __shared__ char sm[];
    const uint32_t sbase = smem_u32(sm);
    const int t = threadIdx.x, lane = t & 31, w = t >> 5;
    const int wm = w & 3, wn = w >> 2;
    const int m0 = blockIdx.y << 7, n0 = blockIdx.x << 7;
    const char* Ap = (const char*)(A + (size_t)m0 * K);
    const char* Bp = (const char*)(B + (size_t)n0 * K);
    const size_t krow = (size_t)K * 2;
    const int KC = K >> 6;

    // per-thread cp.async source/dest patterns (4 iters x (A,B))
    const int ldr = t >> 3;              // 0..31 base row
    const int lc16 = (t & 7) << 4;       // byte col 0..112

    auto load_stage = [&](int c, int buf) {
        const uint32_t ab = sbase + buf * 32768;
        const uint32_t bb = ab + 16384;
        const char* As = Ap + c * 128;
        const char* Bs = Bp + c * 128;
        #pragma unroll
        for (int i = 0; i < 4; i++) {
            const int row = ldr + (i << 5);
            const uint32_t off = sw128((row << 7) + lc16);
            cp16(ab + off, As + (size_t)row * krow + lc16);
            cp16(bb + off, Bs + (size_t)row * krow + lc16);
        }
        asm volatile("cp.async.commit_group;" ::: "memory");
    };

    load_stage(0, 0);
    load_stage(1, 1);

    float acc[2][8][4] = {};

    // ldmatrix per-thread row/col patterns
    const int arow0 = wm * 32 + (lane & 15);        // + mt*16
    const int acb   = (lane >> 4) << 4;             // 0 or 16 bytes
    const int nrow0 = wn * 64 + ((lane >> 4) & 1) * 8 + (lane & 7);  // + nt4*16
    const int bcb   = ((lane >> 3) & 1) << 4;       // 0 or 16 bytes

    for (int c = 0; c < KC; c++) {
        const int buf = c & 1;
        if (c + 1 < KC) asm volatile("cp.async.wait_group 1;" ::: "memory");
        else            asm volatile("cp.async.wait_group 0;" ::: "memory");
        __syncthreads();

        const uint32_t ab = sbase + buf * 32768;
        const uint32_t bb = ab + 16384;
        #pragma unroll
        for (int ks = 0; ks < 4; ks++) {
            uint32_t afr[2][4];
            #pragma unroll
            for (int mt = 0; mt < 2; mt++)
                ldsm4(afr[mt], ab + sw128(((arow0 + mt * 16) << 7) + ks * 32 + acb));
            uint32_t bfr[4][4];
            #pragma unroll
            for (int nt4 = 0; nt4 < 4; nt4++)
                ldsm4(bfr[nt4], bb + sw128(((nrow0 + nt4 * 16) << 7) + ks * 32 + bcb));
            #pragma unroll
            for (int mt = 0; mt < 2; mt++)
                #pragma unroll
                for (int nt = 0; nt < 8; nt++)
                    mma16816(acc[mt][nt], afr[mt],
                             bfr[nt >> 1][(nt & 1) * 2], bfr[nt >> 1][(nt & 1) * 2 + 1]);
        }
        __syncthreads();
        if (c + 2 < KC) load_stage(c + 2, buf);
    }

    // epilogue: fragment -> gmem with bias (+relu)
    const int erow = m0 + wm * 32 + (lane >> 2);
    const int ecol = n0 + wn * 64 + ((lane & 3) << 1);
    #pragma unroll
    for (int nt = 0; nt < 8; nt++) {
        const int gn = ecol + nt * 8;
        const float2 bb2 = *(const float2*)(bias + gn);
        #pragma unroll
        for (int mt = 0; mt < 2; mt++) {
            #pragma unroll
            for (int half = 0; half < 2; half++) {
                float v0 = acc[mt][nt][half * 2 + 0] + bb2.x;
                float v1 = acc[mt][nt][half * 2 + 1] + bb2.y;
                if (RELU) { v0 = fmaxf(v0, 0.f); v1 = fmaxf(v1, 0.f); }
                const int gm = erow + mt * 16 + half * 8;
                *(float2*)(C + (size_t)gm * ldc + gn) = make_float2(v0, v1);
            }
        }
    }
}

// ---------------- split-float kernels ---------------------------------------
// in [R,K] fp32 -> out [R,3K] bf16.  BSTYLE=0: [hi|hi|lo]; BSTYLE=1: [hi|lo|hi]
template<int BSTYLE>
__global__ void split_ab(const float* __restrict__ in, __nv_bfloat16* __restrict__ out,
                         int kshift)
{
    const int K = 1 << kshift;
    const size_t i = ((size_t)blockIdx.x * blockDim.x + threadIdx.x) << 2;
    const size_t rrow = i >> kshift;
    const int k = (int)(i & (K - 1));
    const float4 v = *(const float4*)(in + i);
    float vv[4] = {v.x, v.y, v.z, v.w};
    union { __nv_bfloat16 b[4]; uint2 u; } hu, lu;
    #pragma unroll
    for (int j = 0; j < 4; j++) {
        hu.b[j] = __float2bfloat16(vv[j]);
        lu.b[j] = __float2bfloat16(vv[j] - __bfloat162float(hu.b[j]));
    }
    __nv_bfloat16* o = out + rrow * (3 * (size_t)K) + k;
    *(uint2*)(o)         = hu.u;
    *(uint2*)(o + K)     = BSTYLE ? lu.u : hu.u;
    *(uint2*)(o + 2 * K) = BSTYLE ? hu.u : lu.u;
}

// ---------------- fp32 SIMT GEMM for Wc = [Wf_l@Wl_out | Wf_g@Wg_out] ------
__global__ void __launch_bounds__(256)
wc_gemm(const float* __restrict__ Wf, const float* __restrict__ Wl_out,
        const float* __restrict__ Wg_out, float* __restrict__ Wc)
{
    __shared__ float As[16][68];
    __shared__ float Bs[16][68];
    const int g = blockIdx.z;
    const float* A = Wf + (g ? Ee : 0);
    const float* W = g ? Wg_out : Wl_out;
    float* C = Wc + (g ? Ee : 0);
    const int t = threadIdx.x, tx = t & 15, ty = t >> 4;
    const int m0 = blockIdx.y * 64, n0 = blockIdx.x * 64;
    const int lr = t >> 2, lk = (t & 3) << 2;
    float acc[4][4] = {};
    for (int k0 = 0; k0 < Ee; k0 += 16) {
        {
            float4 v = *(const float4*)(A + (size_t)(m0 + lr) * (2 * Ee) + k0 + lk);
            As[lk + 0][lr] = v.x; As[lk + 1][lr] = v.y;
            As[lk + 2][lr] = v.z; As[lk + 3][lr] = v.w;
        }
        {
            const int kk = t >> 4, cc = (t & 15) << 2;
            *(float4*)&Bs[kk][cc] = *(const float4*)(W + (size_t)(k0 + kk) * Ee + n0 + cc);
        }
        __syncthreads();
        #pragma unroll
        for (int kk = 0; kk < 16; kk++) {
            float4 a = *(const float4*)&As[kk][ty << 2];
            float4 b = *(const float4*)&Bs[kk][tx << 2];
            float av[4] = {a.x, a.y, a.z, a.w};
            float bv[4] = {b.x, b.y, b.z, b.w};
            #pragma unroll
            for (int i = 0; i < 4; i++)
                #pragma unroll
                for (int j = 0; j < 4; j++)
                    acc[i][j] = fmaf(av[i], bv[j], acc[i][j]);
        }
        __syncthreads();
    }
    #pragma unroll
    for (int i = 0; i < 4; i++)
        *(float4*)(C + (size_t)(m0 + (ty << 2) + i) * (2 * Ee) + n0 + (tx << 2)) =
            make_float4(acc[i][0], acc[i][1], acc[i][2], acc[i][3]);
}

// ---------------- combined bias ---------------------------------------------
__global__ void bias_combine_kernel(const float* __restrict__ Wf,
                                    const float* __restrict__ bl,
                                    const float* __restrict__ bg,
                                    const float* __restrict__ bf)
{
    int o = blockIdx.x * blockDim.x + threadIdx.x;
    if (o >= Ee) return;
    float acc = bf[o];
    const float* row = Wf + (size_t)o * (2 * Ee);
    for (int j = 0; j < Ee; j++)
        acc += row[j] * bl[j] + row[Ee + j] * bg[j];
    g_bc[o] = acc;
}

// ---------------- local (banded) attention ----------------------------------
__global__ void __launch_bounds__(256)
local_attn_kernel(const float* __restrict__ qkv)
{
    const int warp = (blockIdx.x * blockDim.x + threadIdx.x) >> 5;
    const int lane = threadIdx.x & 31;
    const int q  = warp & (Ss - 1);
    const int bh = warp >> 10;
    const int b  = bh >> 3, h = bh & 7;

    const float* base = qkv + (size_t)(b * Ss) * QKVN + h * DHd;
    const float* qrow = base + (size_t)q * QKVN;
    const float q0 = qrow[lane], q1 = qrow[lane + 32];

    float s[7];
    float mmax = -1e30f;
    #pragma unroll
    for (int jj = 0; jj < 7; jj++) {
        const int j = q - LOCALW + jj;
        const bool valid = (j >= 0) && (j < Ss);
        float d = 0.f;
        if (valid) {
            const float* krow = base + (size_t)j * QKVN + Ee;
            d = q0 * krow[lane] + q1 * krow[lane + 32];
        }
        #pragma unroll
        for (int off = 16; off; off >>= 1)
            d += __shfl_xor_sync(0xffffffffu, d, off);
        d = valid ? d * 0.125f : -1e30f;
        s[jj] = d;
        mmax = fmaxf(mmax, d);
    }
    float sum = 0.f;
    #pragma unroll
    for (int jj = 0; jj < 7; jj++) { s[jj] = __expf(s[jj] - mmax); sum += s[jj]; }
    const float inv = 1.f / sum;
    float o0 = 0.f, o1 = 0.f;
    #pragma unroll
    for (int jj = 0; jj < 7; jj++) {
        const int j = q - LOCALW + jj;
        if (j >= 0 && j < Ss) {
            const float* vrow = base + (size_t)j * QKVN + 2 * Ee;
            o0 = fmaf(s[jj], vrow[lane],      o0);
            o1 = fmaf(s[jj], vrow[lane + 32], o1);
        }
    }
    float* out = g_attn + (size_t)(b * Ss + q) * (2 * Ee) + h * DHd;
    out[lane]      = o0 * inv;
    out[lane + 32] = o1 * inv;
}

// ---------------- global attention, flash-style fp32 ------------------------
#define FP 68
#define FSMEM (4 * 64 * FP * (int)sizeof(float))

__global__ void __launch_bounds__(256)
global_attn_kernel(const float* __restrict__ qkv)
{
    extern __shared__ float smf[];
    float* QsT = smf;
    float* KsT = smf + 64 * FP;
    float* Vs  = smf + 2 * 64 * FP;
    float* Ps  = smf + 3 * 64 * FP;

    const int t  = threadIdx.x;
    const int tx = t & 15, ty = t >> 4;
    const int bh = blockIdx.y;
    const int b  = bh >> 3, h = bh & 7;
    const int q0 = blockIdx.x << 6;
    const float* base = qkv + (size_t)(b * Ss) * QKVN + h * DHd;

    #pragma unroll
    for (int u = 0; u < 4; u++) {
        const int idx = t + (u << 8);
        const int r = idx >> 4;
        const int c = (idx & 15) << 2;
        float4 v = *(const float4*)(base + (size_t)(q0 + r) * QKVN + c);
        QsT[(c + 0) * FP + r] = v.x * 0.125f;
        QsT[(c + 1) * FP + r] = v.y * 0.125f;
        QsT[(c + 2) * FP + r] = v.z * 0.125f;
        QsT[(c + 3) * FP + r] = v.w * 0.125f;
    }

    float o[4][4] = {};
    float mi[4] = {-INFINITY, -INFINITY, -INFINITY, -INFINITY};
    float li[4] = {0.f, 0.f, 0.f, 0.f};

    for (int kt = 0; kt < Ss; kt += 64) {
        #pragma unroll
        for (int u = 0; u < 4; u++) {
            const int idx = t + (u << 8);
            const int r = idx >> 4;
            const int c = (idx & 15) << 2;
            float4 vk = *(const float4*)(base + (size_t)(kt + r) * QKVN + Ee + c);
            KsT[(c + 0) * FP + r] = vk.x;
            KsT[(c + 1) * FP + r] = vk.y;
            KsT[(c + 2) * FP + r] = vk.z;
            KsT[(c + 3) * FP + r] = vk.w;
            float4 vv = *(const float4*)(base + (size_t)(kt + r) * QKVN + 2 * Ee + c);
            *(float4*)(Vs + r * FP + c) = vv;
        }
        __syncthreads();

        float s[4][4] = {};
        #pragma unroll 16
        for (int kk = 0; kk < 64; kk++) {
            float4 a = *(const float4*)(QsT + kk * FP + (ty << 2));
            float4 bq = *(const float4*)(KsT + kk * FP + (tx << 2));
            float av[4] = {a.x, a.y, a.z, a.w};
            float bv[4] = {bq.x, bq.y, bq.z, bq.w};
            #pragma unroll
            for (int i = 0; i < 4; i++)
                #pragma unroll
                for (int j = 0; j < 4; j++)
                    s[i][j] = fmaf(av[i], bv[j], s[i][j]);
        }

        #pragma unroll
        for (int i = 0; i < 4; i++) {
            float rm = fmaxf(fmaxf(s[i][0], s[i][1]), fmaxf(s[i][2], s[i][3]));
            #pragma unroll
            for (int off = 8; off; off >>= 1)
                rm = fmaxf(rm, __shfl_xor_sync(0xffffffffu, rm, off));
            const float mnew = fmaxf(mi[i], rm);
            const float sc = __expf(mi[i] - mnew);
            mi[i] = mnew;
            float rs = 0.f;
            #pragma unroll
            for (int j = 0; j < 4; j++) { s[i][j] = __expf(s[i][j] - mnew); rs += s[i][j]; }
            #pragma unroll
            for (int off = 8; off; off >>= 1)
                rs += __shfl_xor_sync(0xffffffffu, rs, off);
            li[i] = li[i] * sc + rs;
            #pragma unroll
            for (int j = 0; j < 4; j++) o[i][j] *= sc;
            *(float4*)(Ps + ((ty << 2) + i) * FP + (tx << 2)) =
                make_float4(s[i][0], s[i][1], s[i][2], s[i][3]);
        }
        __syncthreads();

        #pragma unroll 16
        for (int kk = 0; kk < 64; kk++) {
            float av[4];
            #pragma unroll
            for (int i = 0; i < 4; i++)
                av[i] = Ps[((ty << 2) + i) * FP + kk];
            float4 bv4 = *(const float4*)(Vs + kk * FP + (tx << 2));
            float bv[4] = {bv4.x, bv4.y, bv4.z, bv4.w};
            #pragma unroll
            for (int i = 0; i < 4; i++)
                #pragma unroll
                for (int j = 0; j < 4; j++)
                    o[i][j] = fmaf(av[i], bv[j], o[i][j]);
        }
        __syncthreads();
    }

    #pragma unroll
    for (int i = 0; i < 4; i++) {
        const float inv = 1.f / li[i];
        *(float4*)(g_attn + (size_t)(b * Ss + q0 + (ty << 2) + i) * (2 * Ee)
                   + Ee + h * DHd + (tx << 2)) =
            make_float4(o[i][0] * inv, o[i][1] * inv, o[i][2] * inv, o[i][3] * inv);
    }
}

// ---------------- launcher ---------------------------------------------------
extern "C" void kernel_launch(void* const* d_in, const int* in_sizes, int n_in,
                              void* d_out, int out_size)
{
    (void)in_sizes; (void)n_in; (void)out_size;
    const float* x      = (const float*)d_in[0];
    const float* Wl_in  = (const float*)d_in[1];
    const float* bl_in  = (const float*)d_in[2];
    const float* Wl_out = (const float*)d_in[3];
    const float* bl_out = (const float*)d_in[4];
    const float* Wg_in  = (const float*)d_in[5];
    const float* bg_in  = (const float*)d_in[6];
    const float* Wg_out = (const float*)d_in[7];
    const float* bg_out = (const float*)d_in[8];
    const float* Wf     = (const float*)d_in[9];
    const float* bf     = (const float*)d_in[10];
    float* out = (float*)d_out;

    float *qkv_l, *qkv_g, *attn, *Wc, *bc;
    __nv_bfloat16 *A1, *B1l, *B1g, *A2, *B2;
    cudaGetSymbolAddress((void**)&qkv_l, g_qkv_l);
    cudaGetSymbolAddress((void**)&qkv_g, g_qkv_g);
    cudaGetSymbolAddress((void**)&attn,  g_attn);
    cudaGetSymbolAddress((void**)&Wc,    g_Wc);
    cudaGetSymbolAddress((void**)&bc,    g_bc);
    cudaGetSymbolAddress((void**)&A1,    g_A1);
    cudaGetSymbolAddress((void**)&B1l,   g_B1l);
    cudaGetSymbolAddress((void**)&B1g,   g_B1g);
    cudaGetSymbolAddress((void**)&A2,    g_A2);
    cudaGetSymbolAddress((void**)&B2,    g_B2);

    cudaFuncSetAttribute(global_attn_kernel,
                         cudaFuncAttributeMaxDynamicSharedMemorySize, FSMEM);
    cudaFuncSetAttribute(mma_gemm<false>,
                         cudaFuncAttributeMaxDynamicSharedMemorySize, MMA_SMEM);
    cudaFuncSetAttribute(mma_gemm<true>,
                         cudaFuncAttributeMaxDynamicSharedMemorySize, MMA_SMEM);

    // 1) splits of x and input-proj weights
    split_ab<0><<<(Mm * Ee) / 4 / 256, 256>>>(x, A1, 9);          // x: [8192,512]
    split_ab<1><<<(QKVN * Ee) / 4 / 256, 256>>>(Wl_in, B1l, 9);   // [1536,512]
    split_ab<1><<<(QKVN * Ee) / 4 / 256, 256>>>(Wg_in, B1g, 9);

    // 2) combined epilogue weights + bias, then split
    wc_gemm<<<dim3(8, 8, 2), 256>>>(Wf, Wl_out, Wg_out, Wc);
    bias_combine_kernel<<<2, 256>>>(Wf, bl_out, bg_out, bf);
    split_ab<1><<<(Ee * 2 * Ee) / 4 / 256, 256>>>(Wc, B2, 10);    // [512,1024]

    // 3) QKV projections on tensor cores (split-bf16, K'=1536)
    mma_gemm<false><<<dim3(QKVN / 128, Mm / 128), 256, MMA_SMEM>>>(
        A1, B1l, bl_in, qkv_l, 3 * Ee, QKVN);
    mma_gemm<false><<<dim3(QKVN / 128, Mm / 128), 256, MMA_SMEM>>>(
        A1, B1g, bg_in, qkv_g, 3 * Ee, QKVN);

    // 4) attention (fp32 SIMT)
    local_attn_kernel<<<(Bb * Hh * Ss) / 8, 256>>>(qkv_l);
    global_attn_kernel<<<dim3(Ss / 64, Bb * Hh), 256, FSMEM>>>(qkv_g);

    // 5) split attn output, final fused projection + ReLU on tensor cores
    split_ab<0><<<(Mm * 2 * Ee) / 4 / 256, 256>>>(attn, A2, 10);  // [8192,1024]
    mma_gemm<true><<<dim3(Ee / 128, Mm / 128), 256, MMA_SMEM>>>(
        A2, B2, bc, out, 3 * 2 * Ee, Ee);
}

// round 4
// speedup vs baseline: 2.4870x; 1.4702x over previous
#include <cuda_runtime.h>
#include <cuda_bf16.h>
#include <math.h>
#include <stdint.h>

// Problem constants
#define Bb   8
#define Ss   1024
#define Ee   512
#define Hh   8
#define DHd  64
#define Mm   (Bb * Ss)        // 8192
#define QKVN (3 * Ee)         // 1536
#define LOCALW 3

// ---------------- scratch (device globals) ----------------------------------
__device__ float g_qkv_l[(size_t)Mm * QKVN];
__device__ float g_qkv_g[(size_t)Mm * QKVN];
__device__ float g_attn [(size_t)Mm * 2 * Ee];
__device__ float g_Wc   [(size_t)Ee * 2 * Ee];
__device__ float g_bc   [Ee];
__device__ __nv_bfloat16 g_A1 [(size_t)Mm * 3 * Ee];
__device__ __nv_bfloat16 g_B1l[(size_t)QKVN * 3 * Ee];
__device__ __nv_bfloat16 g_B1g[(size_t)QKVN * 3 * Ee];
__device__ __nv_bfloat16 g_A2 [(size_t)Mm * 3 * 2 * Ee];
__device__ __nv_bfloat16 g_B2 [(size_t)Ee * 3 * 2 * Ee];
__device__ __nv_bfloat16 g_qk_h[(size_t)Mm * 1024];        // Q|K hi  [8192,1024]
__device__ __nv_bfloat16 g_qk_l[(size_t)Mm * 1024];        // Q|K lo
__device__ __nv_bfloat16 g_vt_h[(size_t)64 * 64 * Ss];     // V^T hi  [bh*64+d][s]
__device__ __nv_bfloat16 g_vt_l[(size_t)64 * 64 * Ss];     // V^T lo

// ---------------- PTX helpers (base ISA only) --------------------------------
__device__ __forceinline__ uint32_t smem_u32(const void* p) {
    uint32_t a;
    asm("{ .reg .u64 t; cvta.to.shared.u64 t, %1; cvt.u32.u64 %0, t; }"
        : "=r"(a) : "l"(p));
    return a;
}
__device__ __forceinline__ uint32_t sw128(uint32_t o) { return o ^ ((o >> 3) & 0x70); }

__device__ __forceinline__ void cp16(uint32_t dst, const void* src) {
    asm volatile("cp.async.cg.shared.global [%0], [%1], 16;"
                 :: "r"(dst), "l"(src) : "memory");
}
__device__ __forceinline__ void ldsm4(uint32_t* d, uint32_t a) {
    asm volatile("ldmatrix.sync.aligned.m8n8.x4.shared.b16 {%0,%1,%2,%3}, [%4];"
                 : "=r"(d[0]), "=r"(d[1]), "=r"(d[2]), "=r"(d[3]) : "r"(a));
}
__device__ __forceinline__ void mma16816(float* c, const uint32_t* a,
                                         uint32_t b0, uint32_t b1) {
    asm volatile("mma.sync.aligned.m16n8k16.row.col.f32.bf16.bf16.f32 "
                 "{%0,%1,%2,%3}, {%4,%5,%6,%7}, {%8,%9}, {%0,%1,%2,%3};"
                 : "+f"(c[0]), "+f"(c[1]), "+f"(c[2]), "+f"(c[3])
                 : "r"(a[0]), "r"(a[1]), "r"(a[2]), "r"(a[3]), "r"(b0), "r"(b1));
}
// pack two floats into bf16x2 (lo=a, hi=b), return residuals
__device__ __forceinline__ uint32_t pack_bf2(float a, float b, float& ra, float& rb) {
    __nv_bfloat16 ha = __float2bfloat16(a), hb = __float2bfloat16(b);
    ra = a - __bfloat162float(ha);
    rb = b - __bfloat162float(hb);
    return ((uint32_t)*(uint16_t*)&hb << 16) | (uint32_t)*(uint16_t*)&ha;
}
__device__ __forceinline__ uint32_t pack_bf2n(float a, float b) {
    __nv_bfloat16 ha = __float2bfloat16(a), hb = __float2bfloat16(b);
    return ((uint32_t)*(uint16_t*)&hb << 16) | (uint32_t)*(uint16_t*)&ha;
}

// ---------------- mma.sync bf16 GEMM (validated round 3) --------------------
#define MMA_SMEM 65536

template<bool RELU>
__global__ void __launch_bounds__(256)
mma_gemm(const __nv_bfloat16* __restrict__ A, const __nv_bfloat16* __restrict__ B,
         const float* __restrict__ bias, float* __restrict__ C, int K, int ldc)
{
    extern __shared__ char sm[];
    const uint32_t sbase = smem_u32(sm);
    const int t = threadIdx.x, lane = t & 31, w = t >> 5;
    const int wm = w & 3, wn = w >> 2;
    const int m0 = blockIdx.y << 7, n0 = blockIdx.x << 7;
    const char* Ap = (const char*)(A + (size_t)m0 * K);
    const char* Bp = (const char*)(B + (size_t)n0 * K);
    const size_t krow = (size_t)K * 2;
    const int KC = K >> 6;

    const int ldr = t >> 3;
    const int lc16 = (t & 7) << 4;

    auto load_stage = [&](int c, int buf) {
        const uint32_t ab = sbase + buf * 32768;
        const uint32_t bb = ab + 16384;
        const char* As = Ap + c * 128;
        const char* Bs = Bp + c * 128;
        #pragma unroll
        for (int i = 0; i < 4; i++) {
            const int row = ldr + (i << 5);
            const uint32_t off = sw128((row << 7) + lc16);
            cp16(ab + off, As + (size_t)row * krow + lc16);
            cp16(bb + off, Bs + (size_t)row * krow + lc16);
        }
        asm volatile("cp.async.commit_group;" ::: "memory");
    };

    load_stage(0, 0);
    load_stage(1, 1);

    float acc[2][8][4] = {};

    const int arow0 = wm * 32 + (lane & 15);
    const int acb   = (lane >> 4) << 4;
    const int nrow0 = wn * 64 + ((lane >> 4) & 1) * 8 + (lane & 7);
    const int bcb   = ((lane >> 3) & 1) << 4;

    for (int c = 0; c < KC; c++) {
        const int buf = c & 1;
        if (c + 1 < KC) asm volatile("cp.async.wait_group 1;" ::: "memory");
        else            asm volatile("cp.async.wait_group 0;" ::: "memory");
        __syncthreads();

        const uint32_t ab = sbase + buf * 32768;
        const uint32_t bb = ab + 16384;
        #pragma unroll
        for (int ks = 0; ks < 4; ks++) {
            uint32_t afr[2][4];
            #pragma unroll
            for (int mt = 0; mt < 2; mt++)
                ldsm4(afr[mt], ab + sw128(((arow0 + mt * 16) << 7) + ks * 32 + acb));
            uint32_t bfr[4][4];
            #pragma unroll
            for (int nt4 = 0; nt4 < 4; nt4++)
                ldsm4(bfr[nt4], bb + sw128(((nrow0 + nt4 * 16) << 7) + ks * 32 + bcb));
            #pragma unroll
            for (int mt = 0; mt < 2; mt++)
                #pragma unroll
                for (int nt = 0; nt < 8; nt++)
                    mma16816(acc[mt][nt], afr[mt],
                             bfr[nt >> 1][(nt & 1) * 2], bfr[nt >> 1][(nt & 1) * 2 + 1]);
        }
        __syncthreads();
        if (c + 2 < KC) load_stage(c + 2, buf);
    }

    const int erow = m0 + wm * 32 + (lane >> 2);
    const int ecol = n0 + wn * 64 + ((lane & 3) << 1);
    #pragma unroll
    for (int nt = 0; nt < 8; nt++) {
        const int gn = ecol + nt * 8;
        const float2 bb2 = *(const float2*)(bias + gn);
        #pragma unroll
        for (int mt = 0; mt < 2; mt++) {
            #pragma unroll
            for (int half = 0; half < 2; half++) {
                float v0 = acc[mt][nt][half * 2 + 0] + bb2.x;
                float v1 = acc[mt][nt][half * 2 + 1] + bb2.y;
                if (RELU) { v0 = fmaxf(v0, 0.f); v1 = fmaxf(v1, 0.f); }
                const int gm = erow + mt * 16 + half * 8;
                *(float2*)(C + (size_t)gm * ldc + gn) = make_float2(v0, v1);
            }
        }
    }
}

// ---------------- split-float kernels ----------------------------------------
template<int BSTYLE>
__global__ void split_ab(const float* __restrict__ in, __nv_bfloat16* __restrict__ out,
                         int kshift)
{
    const int K = 1 << kshift;
    const size_t i = ((size_t)blockIdx.x * blockDim.x + threadIdx.x) << 2;
    const size_t rrow = i >> kshift;
    const int k = (int)(i & (K - 1));
    const float4 v = *(const float4*)(in + i);
    float vv[4] = {v.x, v.y, v.z, v.w};
    union { __nv_bfloat16 b[4]; uint2 u; } hu, lu;
    #pragma unroll
    for (int j = 0; j < 4; j++) {
        hu.b[j] = __float2bfloat16(vv[j]);
        lu.b[j] = __float2bfloat16(vv[j] - __bfloat162float(hu.b[j]));
    }
    __nv_bfloat16* o = out + rrow * (3 * (size_t)K) + k;
    *(uint2*)(o)         = hu.u;
    *(uint2*)(o + K)     = BSTYLE ? lu.u : hu.u;
    *(uint2*)(o + 2 * K) = BSTYLE ? hu.u : lu.u;
}

// split Q|K columns (first 1024 of 1536) of qkv_g into compact hi/lo arrays
__global__ void split_qk(const float* __restrict__ qkv,
                         __nv_bfloat16* __restrict__ oh, __nv_bfloat16* __restrict__ ol)
{
    const size_t i = ((size_t)blockIdx.x * 256 + threadIdx.x) << 2;
    const size_t row = i >> 10;
    const int col = (int)(i & 1023);
    const float4 v = *(const float4*)(qkv + row * QKVN + col);
    float vv[4] = {v.x, v.y, v.z, v.w};
    union { __nv_bfloat16 b[4]; uint2 u; } hu, lu;
    #pragma unroll
    for (int j = 0; j < 4; j++) {
        hu.b[j] = __float2bfloat16(vv[j]);
        lu.b[j] = __float2bfloat16(vv[j] - __bfloat162float(hu.b[j]));
    }
    *(uint2*)(oh + row * 1024 + col) = hu.u;
    *(uint2*)(ol + row * 1024 + col) = lu.u;
}

// transpose + split V: qkv_g[...,2E+h*64+d] -> vt[(bh*64+d)][s]
__global__ void __launch_bounds__(256)
vt_split(const float* __restrict__ qkv,
         __nv_bfloat16* __restrict__ vh, __nv_bfloat16* __restrict__ vl)
{
    __shared__ float tile[64][65];
    const int t = threadIdx.x;
    const int bh = blockIdx.y, b = bh >> 3, h = bh & 7;
    const int s0 = blockIdx.x << 6;
    #pragma unroll
    for (int i = 0; i < 4; i++) {
        const int idx = t + (i << 8);
        const int row = idx >> 4, c4 = (idx & 15) << 2;
        float4 v = *(const float4*)(qkv + (size_t)(b * Ss + s0 + row) * QKVN
                                    + 2 * Ee + h * 64 + c4);
        tile[row][c4] = v.x; tile[row][c4 + 1] = v.y;
        tile[row][c4 + 2] = v.z; tile[row][c4 + 3] = v.w;
    }
    __syncthreads();
    #pragma unroll
    for (int i = 0; i < 4; i++) {
        const int idx = t + (i << 8);
        const int d = idx >> 4, sc = (idx & 15) << 2;
        uint16_t hh[4], ll[4];
        #pragma unroll
        for (int k = 0; k < 4; k++) {
            const float f = tile[sc + k][d];
            __nv_bfloat16 hb = __float2bfloat16(f);
            const float lf = f - __bfloat162float(hb);
            __nv_bfloat16 lb = __float2bfloat16(lf);
            hh[k] = *(uint16_t*)&hb; ll[k] = *(uint16_t*)&lb;
        }
        uint2 hv = make_uint2((uint32_t)hh[0] | ((uint32_t)hh[1] << 16),
                              (uint32_t)hh[2] | ((uint32_t)hh[3] << 16));
        uint2 lv = make_uint2((uint32_t)ll[0] | ((uint32_t)ll[1] << 16),
                              (uint32_t)ll[2] | ((uint32_t)ll[3] << 16));
        *(uint2*)(vh + (size_t)(bh * 64 + d) * Ss + s0 + sc) = hv;
        *(uint2*)(vl + (size_t)(bh * 64 + d) * Ss + s0 + sc) = lv;
    }
}

// ---------------- flash attention on tensor cores (split-bf16) --------------
// grid (S/128, B*H), 256 threads. CTA: 128 queries; loop over 16 key tiles of 64.
#define AT_SMEM 98304

#define S_TERM(AF, KB)                                                          \
    _Pragma("unroll")                                                           \
    for (int ks = 0; ks < 4; ks++) {                                            \
        uint32_t bfr[4][4];                                                     \
        _Pragma("unroll")                                                       \
        for (int n4 = 0; n4 < 4; n4++)                                          \
            ldsm4(bfr[n4], (KB) + sw128(((nrow + n4 * 16) << 7) + ks * 32 + bcb)); \
        _Pragma("unroll")                                                       \
        for (int nt = 0; nt < 8; nt++)                                          \
            mma16816(sA[nt], AF[ks],                                            \
                     bfr[nt >> 1][(nt & 1) * 2], bfr[nt >> 1][(nt & 1) * 2 + 1]); \
    }

__global__ void __launch_bounds__(256)
flash_attn(const __nv_bfloat16* __restrict__ qkh, const __nv_bfloat16* __restrict__ qkl,
           const __nv_bfloat16* __restrict__ vth, const __nv_bfloat16* __restrict__ vtl)
{
    extern __shared__ char sm[];
    const uint32_t sb = smem_u32(sm);
    const int t = threadIdx.x, lane = t & 31, w = t >> 5;
    const int bh = blockIdx.y, b = bh >> 3, h = bh & 7;
    const int q0 = blockIdx.x << 7;
    const uint32_t Qh = sb, Ql = sb + 16384;

    // ---- Q loads (hi/lo), group 0
    {
        const char* srch = (const char*)(qkh + (size_t)(b * Ss + q0) * 1024 + h * 64);
        const char* srcl = (const char*)(qkl + (size_t)(b * Ss + q0) * 1024 + h * 64);
        #pragma unroll
        for (int i = 0; i < 4; i++) {
            const int idx = t + (i << 8);
            const int row = idx >> 3, ch = (idx & 7) << 4;
            const uint32_t off = sw128((row << 7) | ch);
            cp16(Qh + off, srch + (size_t)row * 2048 + ch);
            cp16(Ql + off, srcl + (size_t)row * 2048 + ch);
        }
        asm volatile("cp.async.commit_group;" ::: "memory");
    }

    auto load_kv = [&](int kt, int buf) {
        const uint32_t bb = sb + 32768 + buf * 32768;
        const char* kh = (const char*)(qkh + (size_t)(b * Ss + kt * 64) * 1024 + 512 + h * 64);
        const char* kl = (const char*)(qkl + (size_t)(b * Ss + kt * 64) * 1024 + 512 + h * 64);
        const char* vh = (const char*)(vth + (size_t)(bh * 64) * Ss + kt * 64);
        const char* vl = (const char*)(vtl + (size_t)(bh * 64) * Ss + kt * 64);
        #pragma unroll
        for (int i = 0; i < 2; i++) {
            const int idx = t + (i << 8);
            const int row = idx >> 3, ch = (idx & 7) << 4;
            const uint32_t off = sw128((row << 7) | ch);
            cp16(bb + off,         kh + (size_t)row * 2048 + ch);
            cp16(bb + 8192 + off,  kl + (size_t)row * 2048 + ch);
            cp16(bb + 16384 + off, vh + (size_t)row * 2048 + ch);
            cp16(bb + 24576 + off, vl + (size_t)row * 2048 + ch);
        }
        asm volatile("cp.async.commit_group;" ::: "memory");
    };
    load_kv(0, 0);
    load_kv(1, 1);

    asm volatile("cp.async.wait_group 2;" ::: "memory");
    __syncthreads();

    // persistent Q fragments
    const int arow = (w << 4) + (lane & 15);
    const int acb  = (lane >> 4) << 4;
    uint32_t qh[4][4], ql[4][4];
    #pragma unroll
    for (int ks = 0; ks < 4; ks++) {
        ldsm4(qh[ks], Qh + sw128((arow << 7) + ks * 32 + acb));
        ldsm4(ql[ks], Ql + sw128((arow << 7) + ks * 32 + acb));
    }

    const int nrow = ((lane >> 4) & 1) * 8 + (lane & 7);
    const int bcb  = ((lane >> 3) & 1) << 4;

    float o[8][4] = {};
    float m0 = -INFINITY, m1 = -INFINITY, l0 = 0.f, l1 = 0.f;

    for (int kt = 0; kt < 16; kt++) {
        const int buf = kt & 1;
        if (kt + 1 < 16) asm volatile("cp.async.wait_group 1;" ::: "memory");
        else             asm volatile("cp.async.wait_group 0;" ::: "memory");
        __syncthreads();
        const uint32_t Kh = sb + 32768 + buf * 32768;
        const uint32_t Kl = Kh + 8192, Vh = Kh + 16384, Vl = Kh + 24576;

        // S = (Qhi+Qlo)(Khi+Klo)^T, 3 terms
        float sA[8][4] = {};
        S_TERM(qh, Kh)
        S_TERM(qh, Kl)
        S_TERM(ql, Kh)

        // fragment softmax (rows r=lane>>2 and r+8)
        float rm0 = -INFINITY, rm1 = -INFINITY;
        #pragma unroll
        for (int nt = 0; nt < 8; nt++) {
            #pragma unroll
            for (int j = 0; j < 4; j++) sA[nt][j] *= 0.125f;
            rm0 = fmaxf(rm0, fmaxf(sA[nt][0], sA[nt][1]));
            rm1 = fmaxf(rm1, fmaxf(sA[nt][2], sA[nt][3]));
        }
        rm0 = fmaxf(rm0, __shfl_xor_sync(0xffffffffu, rm0, 1));
        rm0 = fmaxf(rm0, __shfl_xor_sync(0xffffffffu, rm0, 2));
        rm1 = fmaxf(rm1, __shfl_xor_sync(0xffffffffu, rm1, 1));
        rm1 = fmaxf(rm1, __shfl_xor_sync(0xffffffffu, rm1, 2));
        const float mn0 = fmaxf(m0, rm0), mn1 = fmaxf(m1, rm1);
        const float sc0 = __expf(m0 - mn0), sc1 = __expf(m1 - mn1);
        m0 = mn0; m1 = mn1;

        float ps0 = 0.f, ps1 = 0.f;
        uint32_t phi[4][4], plo[4][4];
        #pragma unroll
        for (int j = 0; j < 4; j++) {      // key k16-tile = ntiles 2j, 2j+1
            float p[2][4];
            #pragma unroll
            for (int e = 0; e < 2; e++) {
                p[e][0] = __expf(sA[2 * j + e][0] - mn0);
                p[e][1] = __expf(sA[2 * j + e][1] - mn0);
                p[e][2] = __expf(sA[2 * j + e][2] - mn1);
                p[e][3] = __expf(sA[2 * j + e][3] - mn1);
                ps0 += p[e][0] + p[e][1];
                ps1 += p[e][2] + p[e][3];
            }
            float r0, r1;
            phi[j][0] = pack_bf2(p[0][0], p[0][1], r0, r1); plo[j][0] = pack_bf2n(r0, r1);
            phi[j][1] = pack_bf2(p[0][2], p[0][3], r0, r1); plo[j][1] = pack_bf2n(r0, r1);
            phi[j][2] = pack_bf2(p[1][0], p[1][1], r0, r1); plo[j][2] = pack_bf2n(r0, r1);
            phi[j][3] = pack_bf2(p[1][2], p[1][3], r0, r1); plo[j][3] = pack_bf2n(r0, r1);
        }
        l0 = l0 * sc0 + ps0;
        l1 = l1 * sc1 + ps1;
        #pragma unroll
        for (int nt = 0; nt < 8; nt++) {
            o[nt][0] *= sc0; o[nt][1] *= sc0;
            o[nt][2] *= sc1; o[nt][3] *= sc1;
        }

        // O += Phi@Vhi + Plo@Vhi + Phi@Vlo
        #pragma unroll
        for (int ks = 0; ks < 4; ks++) {
            uint32_t bv[4][4];
            #pragma unroll
            for (int n4 = 0; n4 < 4; n4++)
                ldsm4(bv[n4], Vh + sw128(((nrow + n4 * 16) << 7) + ks * 32 + bcb));
            #pragma unroll
            for (int nt = 0; nt < 8; nt++) {
                mma16816(o[nt], phi[ks], bv[nt >> 1][(nt & 1) * 2], bv[nt >> 1][(nt & 1) * 2 + 1]);
                mma16816(o[nt], plo[ks], bv[nt >> 1][(nt & 1) * 2], bv[nt >> 1][(nt & 1) * 2 + 1]);
            }
            #pragma unroll
            for (int n4 = 0; n4 < 4; n4++)
                ldsm4(bv[n4], Vl + sw128(((nrow + n4 * 16) << 7) + ks * 32 + bcb));
            #pragma unroll
            for (int nt = 0; nt < 8; nt++)
                mma16816(o[nt], phi[ks], bv[nt >> 1][(nt & 1) * 2], bv[nt >> 1][(nt & 1) * 2 + 1]);
        }
        __syncthreads();
        if (kt + 2 < 16) load_kv(kt + 2, buf);
    }

    // epilogue
    l0 += __shfl_xor_sync(0xffffffffu, l0, 1);
    l0 += __shfl_xor_sync(0xffffffffu, l0, 2);
    l1 += __shfl_xor_sync(0xffffffffu, l1, 1);
    l1 += __shfl_xor_sync(0xffffffffu, l1, 2);
    const float i0 = 1.f / l0, i1 = 1.f / l1;
    const int r = lane >> 2, c2 = (lane & 3) << 1;
    const int row0 = b * Ss + q0 + (w << 4) + r;
    float* ob  = g_attn + (size_t)row0 * 1024 + 512 + h * 64;
    float* ob2 = ob + (size_t)8 * 1024;
    #pragma unroll
    for (int nt = 0; nt < 8; nt++) {
        *(float2*)(ob  + nt * 8 + c2) = make_float2(o[nt][0] * i0, o[nt][1] * i0);
        *(float2*)(ob2 + nt * 8 + c2) = make_float2(o[nt][2] * i1, o[nt][3] * i1);
    }
}

// ---------------- fp32 SIMT GEMM for Wc --------------------------------------
__global__ void __launch_bounds__(256)
wc_gemm(const float* __restrict__ Wf, const float* __restrict__ Wl_out,
        const float* __restrict__ Wg_out, float* __restrict__ Wc)
{
    __shared__ float As[16][68];
    __shared__ float Bs[16][68];
    const int g = blockIdx.z;
    const float* A = Wf + (g ? Ee : 0);
    const float* W = g ? Wg_out : Wl_out;
    float* C = Wc + (g ? Ee : 0);
    const int t = threadIdx.x, tx = t & 15, ty = t >> 4;
    const int m0 = blockIdx.y * 64, n0 = blockIdx.x * 64;
    const int lr = t >> 2, lk = (t & 3) << 2;
    float acc[4][4] = {};
    for (int k0 = 0; k0 < Ee; k0 += 16) {
        {
            float4 v = *(const float4*)(A + (size_t)(m0 + lr) * (2 * Ee) + k0 + lk);
            As[lk + 0][lr] = v.x; As[lk + 1][lr] = v.y;
            As[lk + 2][lr] = v.z; As[lk + 3][lr] = v.w;
        }
        {
            const int kk = t >> 4, cc = (t & 15) << 2;
            *(float4*)&Bs[kk][cc] = *(const float4*)(W + (size_t)(k0 + kk) * Ee + n0 + cc);
        }
        __syncthreads();
        #pragma unroll
        for (int kk = 0; kk < 16; kk++) {
            float4 a = *(const float4*)&As[kk][ty << 2];
            float4 b = *(const float4*)&Bs[kk][tx << 2];
            float av[4] = {a.x, a.y, a.z, a.w};
            float bv[4] = {b.x, b.y, b.z, b.w};
            #pragma unroll
            for (int i = 0; i < 4; i++)
                #pragma unroll
                for (int j = 0; j < 4; j++)
                    acc[i][j] = fmaf(av[i], bv[j], acc[i][j]);
        }
        __syncthreads();
    }
    #pragma unroll
    for (int i = 0; i < 4; i++)
        *(float4*)(C + (size_t)(m0 + (ty << 2) + i) * (2 * Ee) + n0 + (tx << 2)) =
            make_float4(acc[i][0], acc[i][1], acc[i][2], acc[i][3]);
}

// ---------------- combined bias ----------------------------------------------
__global__ void bias_combine_kernel(const float* __restrict__ Wf,
                                    const float* __restrict__ bl,
                                    const float* __restrict__ bg,
                                    const float* __restrict__ bf)
{
    int o = blockIdx.x * blockDim.x + threadIdx.x;
    if (o >= Ee) return;
    float acc = bf[o];
    const float* row = Wf + (size_t)o * (2 * Ee);
    for (int j = 0; j < Ee; j++)
        acc += row[j] * bl[j] + row[Ee + j] * bg[j];
    g_bc[o] = acc;
}

// ---------------- local (banded) attention ------------------------------------
__global__ void __launch_bounds__(256)
local_attn_kernel(const float* __restrict__ qkv)
{
    const int warp = (blockIdx.x * blockDim.x + threadIdx.x) >> 5;
    const int lane = threadIdx.x & 31;
    const int q  = warp & (Ss - 1);
    const int bh = warp >> 10;
    const int b  = bh >> 3, h = bh & 7;

    const float* base = qkv + (size_t)(b * Ss) * QKVN + h * DHd;
    const float* qrow = base + (size_t)q * QKVN;
    const float q0 = qrow[lane], q1 = qrow[lane + 32];

    float s[7];
    float mmax = -1e30f;
    #pragma unroll
    for (int jj = 0; jj < 7; jj++) {
        const int j = q - LOCALW + jj;
        const bool valid = (j >= 0) && (j < Ss);
        float d = 0.f;
        if (valid) {
            const float* krow = base + (size_t)j * QKVN + Ee;
            d = q0 * krow[lane] + q1 * krow[lane + 32];
        }
        #pragma unroll
        for (int off = 16; off; off >>= 1)
            d += __shfl_xor_sync(0xffffffffu, d, off);
        d = valid ? d * 0.125f : -1e30f;
        s[jj] = d;
        mmax = fmaxf(mmax, d);
    }
    float sum = 0.f;
    #pragma unroll
    for (int jj = 0; jj < 7; jj++) { s[jj] = __expf(s[jj] - mmax); sum += s[jj]; }
    const float inv = 1.f / sum;
    float o0 = 0.f, o1 = 0.f;
    #pragma unroll
    for (int jj = 0; jj < 7; jj++) {
        const int j = q - LOCALW + jj;
        if (j >= 0 && j < Ss) {
            const float* vrow = base + (size_t)j * QKVN + 2 * Ee;
            o0 = fmaf(s[jj], vrow[lane],      o0);
            o1 = fmaf(s[jj], vrow[lane + 32], o1);
        }
    }
    float* out = g_attn + (size_t)(b * Ss + q) * (2 * Ee) + h * DHd;
    out[lane]      = o0 * inv;
    out[lane + 32] = o1 * inv;
}

// ---------------- launcher -----------------------------------------------------
extern "C" void kernel_launch(void* const* d_in, const int* in_sizes, int n_in,
                              void* d_out, int out_size)
{
    (void)in_sizes; (void)n_in; (void)out_size;
    const float* x      = (const float*)d_in[0];
    const float* Wl_in  = (const float*)d_in[1];
    const float* bl_in  = (const float*)d_in[2];
    const float* Wl_out = (const float*)d_in[3];
    const float* bl_out = (const float*)d_in[4];
    const float* Wg_in  = (const float*)d_in[5];
    const float* bg_in  = (const float*)d_in[6];
    const float* Wg_out = (const float*)d_in[7];
    const float* bg_out = (const float*)d_in[8];
    const float* Wf     = (const float*)d_in[9];
    const float* bf     = (const float*)d_in[10];
    float* out = (float*)d_out;

    float *qkv_l, *qkv_g, *attn, *Wc, *bc;
    __nv_bfloat16 *A1, *B1l, *B1g, *A2, *B2, *qkh, *qkl, *vth, *vtl;
    cudaGetSymbolAddress((void**)&qkv_l, g_qkv_l);
    cudaGetSymbolAddress((void**)&qkv_g, g_qkv_g);
    cudaGetSymbolAddress((void**)&attn,  g_attn);
    cudaGetSymbolAddress((void**)&Wc,    g_Wc);
    cudaGetSymbolAddress((void**)&bc,    g_bc);
    cudaGetSymbolAddress((void**)&A1,    g_A1);
    cudaGetSymbolAddress((void**)&B1l,   g_B1l);
    cudaGetSymbolAddress((void**)&B1g,   g_B1g);
    cudaGetSymbolAddress((void**)&A2,    g_A2);
    cudaGetSymbolAddress((void**)&B2,    g_B2);
    cudaGetSymbolAddress((void**)&qkh,   g_qk_h);
    cudaGetSymbolAddress((void**)&qkl,   g_qk_l);
    cudaGetSymbolAddress((void**)&vth,   g_vt_h);
    cudaGetSymbolAddress((void**)&vtl,   g_vt_l);

    cudaFuncSetAttribute(mma_gemm<false>,
                         cudaFuncAttributeMaxDynamicSharedMemorySize, MMA_SMEM);
    cudaFuncSetAttribute(mma_gemm<true>,
                         cudaFuncAttributeMaxDynamicSharedMemorySize, MMA_SMEM);
    cudaFuncSetAttribute(flash_attn,
                         cudaFuncAttributeMaxDynamicSharedMemorySize, AT_SMEM);

    // 1) splits of x and input-proj weights
    split_ab<0><<<(Mm * Ee) / 4 / 256, 256>>>(x, A1, 9);
    split_ab<1><<<(QKVN * Ee) / 4 / 256, 256>>>(Wl_in, B1l, 9);
    split_ab<1><<<(QKVN * Ee) / 4 / 256, 256>>>(Wg_in, B1g, 9);

    // 2) combined epilogue weights + bias, then split
    wc_gemm<<<dim3(8, 8, 2), 256>>>(Wf, Wl_out, Wg_out, Wc);
    bias_combine_kernel<<<2, 256>>>(Wf, bl_out, bg_out, bf);
    split_ab<1><<<(Ee * 2 * Ee) / 4 / 256, 256>>>(Wc, B2, 10);

    // 3) QKV projections (tensor cores, split-bf16, K'=1536)
    mma_gemm<false><<<dim3(QKVN / 128, Mm / 128), 256, MMA_SMEM>>>(
        A1, B1l, bl_in, qkv_l, 3 * Ee, QKVN);
    mma_gemm<false><<<dim3(QKVN / 128, Mm / 128), 256, MMA_SMEM>>>(
        A1, B1g, bg_in, qkv_g, 3 * Ee, QKVN);

    // 4) local attention (fp32 SIMT)
    local_attn_kernel<<<(Bb * Hh * Ss) / 8, 256>>>(qkv_l);

    // 5) global attention pre-passes + tensor-core flash attention
    split_qk<<<(Mm * 1024) / 4 / 256, 256>>>(qkv_g, qkh, qkl);
    vt_split<<<dim3(Ss / 64, Bb * Hh), 256>>>(qkv_g, vth, vtl);
    flash_attn<<<dim3(Ss / 128, Bb * Hh), 256, AT_SMEM>>>(qkh, qkl, vth, vtl);

    // 6) split attn output, final fused projection + ReLU (tensor cores)
    split_ab<0><<<(Mm * 2 * Ee) / 4 / 256, 256>>>(attn, A2, 10);
    mma_gemm<true><<<dim3(Ee / 128, Mm / 128), 256, MMA_SMEM>>>(
        A2, B2, bc, out, 3 * 2 * Ee, Ee);
}

// round 5
// speedup vs baseline: 3.3135x; 1.3323x over previous
#include <cuda_runtime.h>
#include <cuda_bf16.h>
#include <math.h>
#include <stdint.h>

// Problem constants
#define Bb   8
#define Ss   1024
#define Ee   512
#define Hh   8
#define DHd  64
#define Mm   (Bb * Ss)        // 8192
#define QKVN (3 * Ee)         // 1536
#define LOCALW 3

// ---------------- scratch (device globals) ----------------------------------
__device__ float g_qkv_l[(size_t)Mm * QKVN];               // local QKV fp32
__device__ float g_vg   [(size_t)Mm * Ee];                 // global V fp32 compact [8192,512]
__device__ float g_Wc   [(size_t)Ee * 2 * Ee];
__device__ float g_bc   [Ee];
__device__ __nv_bfloat16 g_A1 [(size_t)Mm * 3 * Ee];       // x split [hi|hi|lo]
__device__ __nv_bfloat16 g_B1l[(size_t)QKVN * 3 * Ee];     // Wl_in split [hi|lo|hi]
__device__ __nv_bfloat16 g_B1g[(size_t)QKVN * 3 * Ee];
__device__ __nv_bfloat16 g_A2 [(size_t)Mm * 3 * 1024];     // attn split [hi|hi|lo] [8192,3072]
__device__ __nv_bfloat16 g_B2 [(size_t)Ee * 3 * 1024];     // Wc split [hi|lo|hi]
__device__ __nv_bfloat16 g_qk_h[(size_t)Mm * 1024];        // global Q|K hi
__device__ __nv_bfloat16 g_qk_l[(size_t)Mm * 1024];        // global Q|K lo
__device__ __nv_bfloat16 g_vt_h[(size_t)64 * 64 * Ss];     // V^T hi [bh*64+d][s]
__device__ __nv_bfloat16 g_vt_l[(size_t)64 * 64 * Ss];

// ---------------- PTX helpers (base ISA only) --------------------------------
__device__ __forceinline__ uint32_t smem_u32(const void* p) {
    uint32_t a;
    asm("{ .reg .u64 t; cvta.to.shared.u64 t, %1; cvt.u32.u64 %0, t; }"
        : "=r"(a) : "l"(p));
    return a;
}
__device__ __forceinline__ uint32_t sw128(uint32_t o) { return o ^ ((o >> 3) & 0x70); }

__device__ __forceinline__ void cp16(uint32_t dst, const void* src) {
    asm volatile("cp.async.cg.shared.global [%0], [%1], 16;"
                 :: "r"(dst), "l"(src) : "memory");
}
__device__ __forceinline__ void ldsm4(uint32_t* d, uint32_t a) {
    asm volatile("ldmatrix.sync.aligned.m8n8.x4.shared.b16 {%0,%1,%2,%3}, [%4];"
                 : "=r"(d[0]), "=r"(d[1]), "=r"(d[2]), "=r"(d[3]) : "r"(a));
}
__device__ __forceinline__ void mma16816(float* c, const uint32_t* a,
                                         uint32_t b0, uint32_t b1) {
    asm volatile("mma.sync.aligned.m16n8k16.row.col.f32.bf16.bf16.f32 "
                 "{%0,%1,%2,%3}, {%4,%5,%6,%7}, {%8,%9}, {%0,%1,%2,%3};"
                 : "+f"(c[0]), "+f"(c[1]), "+f"(c[2]), "+f"(c[3])
                 : "r"(a[0]), "r"(a[1]), "r"(a[2]), "r"(a[3]), "r"(b0), "r"(b1));
}
__device__ __forceinline__ uint32_t pack_bf2(float a, float b, float& ra, float& rb) {
    __nv_bfloat16 ha = __float2bfloat16(a), hb = __float2bfloat16(b);
    ra = a - __bfloat162float(ha);
    rb = b - __bfloat162float(hb);
    return ((uint32_t)*(uint16_t*)&hb << 16) | (uint32_t)*(uint16_t*)&ha;
}
__device__ __forceinline__ uint32_t pack_bf2n(float a, float b) {
    __nv_bfloat16 ha = __float2bfloat16(a), hb = __float2bfloat16(b);
    return ((uint32_t)*(uint16_t*)&hb << 16) | (uint32_t)*(uint16_t*)&ha;
}

// ======== common 3-stage mma.sync GEMM core (macro to share exactly) ========
// Consumes: sbase, t/lane/w, m0/n0, Ap/Bp (char*), krow, KC. Produces acc.
#define GEMM_CORE()                                                             \
    const int ldr = t >> 3;                                                     \
    const int lc16 = (t & 7) << 4;                                              \
    auto load_stage = [&](int c, int buf) {                                     \
        const uint32_t ab = sbase + buf * 32768;                                \
        const uint32_t bbs = ab + 16384;                                        \
        const char* As = Ap + c * 128;                                          \
        const char* Bs = Bp + c * 128;                                          \
        _Pragma("unroll")                                                       \
        for (int i = 0; i < 4; i++) {                                           \
            const int row = ldr + (i << 5);                                     \
            const uint32_t off = sw128((row << 7) + lc16);                      \
            cp16(ab + off, As + (size_t)row * krow + lc16);                     \
            cp16(bbs + off, Bs + (size_t)row * krow + lc16);                    \
        }                                                                       \
        asm volatile("cp.async.commit_group;" ::: "memory");                    \
    };                                                                          \
    load_stage(0, 0); load_stage(1, 1); load_stage(2, 2);                       \
    float acc[2][8][4] = {};                                                    \
    const int arow0 = wm * 32 + (lane & 15);                                    \
    const int acb   = (lane >> 4) << 4;                                         \
    const int nrow0 = wn * 64 + ((lane >> 4) & 1) * 8 + (lane & 7);             \
    const int bcb   = ((lane >> 3) & 1) << 4;                                   \
    int buf = 0;                                                                \
    for (int c = 0; c < KC; c++) {                                              \
        if (c + 2 < KC)      asm volatile("cp.async.wait_group 2;" ::: "memory"); \
        else if (c + 1 < KC) asm volatile("cp.async.wait_group 1;" ::: "memory"); \
        else                 asm volatile("cp.async.wait_group 0;" ::: "memory"); \
        __syncthreads();                                                        \
        const uint32_t ab = sbase + buf * 32768;                                \
        const uint32_t bbs = ab + 16384;                                        \
        _Pragma("unroll")                                                       \
        for (int ks = 0; ks < 4; ks++) {                                        \
            uint32_t afr[2][4];                                                 \
            _Pragma("unroll")                                                   \
            for (int mt = 0; mt < 2; mt++)                                      \
                ldsm4(afr[mt], ab + sw128(((arow0 + mt * 16) << 7) + ks * 32 + acb)); \
            uint32_t bfr[4][4];                                                 \
            _Pragma("unroll")                                                   \
            for (int nt4 = 0; nt4 < 4; nt4++)                                   \
                ldsm4(bfr[nt4], bbs + sw128(((nrow0 + nt4 * 16) << 7) + ks * 32 + bcb)); \
            _Pragma("unroll")                                                   \
            for (int mt = 0; mt < 2; mt++)                                      \
                _Pragma("unroll")                                               \
                for (int nt = 0; nt < 8; nt++)                                  \
                    mma16816(acc[mt][nt], afr[mt],                              \
                             bfr[nt >> 1][(nt & 1) * 2], bfr[nt >> 1][(nt & 1) * 2 + 1]); \
        }                                                                       \
        __syncthreads();                                                        \
        if (c + 3 < KC) load_stage(c + 3, buf);                                 \
        buf = (buf == 2) ? 0 : buf + 1;                                         \
    }

#define MMA_SMEM 98304

// ---------------- final GEMM: out = relu(A2 @ B2^T + bc) --------------------
template<bool RELU>
__global__ void __launch_bounds__(256)
mma_gemm(const __nv_bfloat16* __restrict__ A, const __nv_bfloat16* __restrict__ B,
         const float* __restrict__ bias, float* __restrict__ C, int K, int ldc)
{
    extern __shared__ char sm[];
    const uint32_t sbase = smem_u32(sm);
    const int t = threadIdx.x, lane = t & 31, w = t >> 5;
    const int wm = w & 3, wn = w >> 2;
    const int m0 = blockIdx.y << 7, n0 = blockIdx.x << 7;
    const char* Ap = (const char*)(A + (size_t)m0 * K);
    const char* Bp = (const char*)(B + (size_t)n0 * K);
    const size_t krow = (size_t)K * 2;
    const int KC = K >> 6;

    GEMM_CORE()

    const int erow = m0 + wm * 32 + (lane >> 2);
    const int ecol = n0 + wn * 64 + ((lane & 3) << 1);
    #pragma unroll
    for (int nt = 0; nt < 8; nt++) {
        const int gn = ecol + nt * 8;
        const float2 bb2 = *(const float2*)(bias + gn);
        #pragma unroll
        for (int mt = 0; mt < 2; mt++) {
            #pragma unroll
            for (int half = 0; half < 2; half++) {
                float v0 = acc[mt][nt][half * 2 + 0] + bb2.x;
                float v1 = acc[mt][nt][half * 2 + 1] + bb2.y;
                if (RELU) { v0 = fmaxf(v0, 0.f); v1 = fmaxf(v1, 0.f); }
                const int gm = erow + mt * 16 + half * 8;
                *(float2*)(C + (size_t)gm * ldc + gn) = make_float2(v0, v1);
            }
        }
    }
}

// ---------------- fused QKV GEMM (both blocks via blockIdx.z) ----------------
// z=0: local -> fp32 qkv_l.  z=1: global -> Q|K hi/lo bf16, V fp32 compact.
__global__ void __launch_bounds__(256)
qkv_fused(const __nv_bfloat16* __restrict__ A,
          const __nv_bfloat16* __restrict__ Bl, const __nv_bfloat16* __restrict__ Bg,
          const float* __restrict__ bl, const float* __restrict__ bg)
{
    extern __shared__ char sm[];
    const uint32_t sbase = smem_u32(sm);
    const int t = threadIdx.x, lane = t & 31, w = t >> 5;
    const int wm = w & 3, wn = w >> 2;
    const int m0 = blockIdx.y << 7, n0 = blockIdx.x << 7;
    const int z = blockIdx.z;
    const int K = 3 * Ee;
    const __nv_bfloat16* B = z ? Bg : Bl;
    const float* bias = z ? bg : bl;
    const char* Ap = (const char*)(A + (size_t)m0 * K);
    const char* Bp = (const char*)(B + (size_t)n0 * K);
    const size_t krow = (size_t)K * 2;
    const int KC = K >> 6;

    GEMM_CORE()

    const int erow = m0 + wm * 32 + (lane >> 2);
    const int ecol = n0 + wn * 64 + ((lane & 3) << 1);
    #pragma unroll
    for (int nt = 0; nt < 8; nt++) {
        const int gn = ecol + nt * 8;
        const float2 bb2 = *(const float2*)(bias + gn);
        #pragma unroll
        for (int mt = 0; mt < 2; mt++) {
            #pragma unroll
            for (int half = 0; half < 2; half++) {
                const float v0 = acc[mt][nt][half * 2 + 0] + bb2.x;
                const float v1 = acc[mt][nt][half * 2 + 1] + bb2.y;
                const int gm = erow + mt * 16 + half * 8;
                if (z == 0) {
                    *(float2*)(g_qkv_l + (size_t)gm * QKVN + gn) = make_float2(v0, v1);
                } else if (n0 < 1024) {
                    float r0, r1;
                    const uint32_t hi = pack_bf2(v0, v1, r0, r1);
                    const uint32_t lo = pack_bf2n(r0, r1);
                    *(uint32_t*)(g_qk_h + (size_t)gm * 1024 + gn) = hi;
                    *(uint32_t*)(g_qk_l + (size_t)gm * 1024 + gn) = lo;
                } else {
                    *(float2*)(g_vg + (size_t)gm * Ee + (gn - 1024)) = make_float2(v0, v1);
                }
            }
        }
    }
}

// ---------------- split-float kernel -----------------------------------------
// in [R,K] fp32 -> out [R,3K] bf16.  BSTYLE=0: [hi|hi|lo]; BSTYLE=1: [hi|lo|hi]
template<int BSTYLE>
__global__ void split_ab(const float* __restrict__ in, __nv_bfloat16* __restrict__ out,
                         int kshift)
{
    const int K = 1 << kshift;
    const size_t i = ((size_t)blockIdx.x * blockDim.x + threadIdx.x) << 2;
    const size_t rrow = i >> kshift;
    const int k = (int)(i & (K - 1));
    const float4 v = *(const float4*)(in + i);
    float vv[4] = {v.x, v.y, v.z, v.w};
    union { __nv_bfloat16 b[4]; uint2 u; } hu, lu;
    #pragma unroll
    for (int j = 0; j < 4; j++) {
        hu.b[j] = __float2bfloat16(vv[j]);
        lu.b[j] = __float2bfloat16(vv[j] - __bfloat162float(hu.b[j]));
    }
    __nv_bfloat16* o = out + rrow * (3 * (size_t)K) + k;
    *(uint2*)(o)         = hu.u;
    *(uint2*)(o + K)     = BSTYLE ? lu.u : hu.u;
    *(uint2*)(o + 2 * K) = BSTYLE ? hu.u : lu.u;
}

// transpose + split V: vg[row][h*64+d] -> vt[(bh*64+d)][s]
__global__ void __launch_bounds__(256)
vt_split(const float* __restrict__ vg,
         __nv_bfloat16* __restrict__ vh, __nv_bfloat16* __restrict__ vl)
{
    __shared__ float tile[64][65];
    const int t = threadIdx.x;
    const int bh = blockIdx.y, b = bh >> 3, h = bh & 7;
    const int s0 = blockIdx.x << 6;
    #pragma unroll
    for (int i = 0; i < 4; i++) {
        const int idx = t + (i << 8);
        const int row = idx >> 4, c4 = (idx & 15) << 2;
        float4 v = *(const float4*)(vg + (size_t)(b * Ss + s0 + row) * Ee + h * 64 + c4);
        tile[row][c4] = v.x; tile[row][c4 + 1] = v.y;
        tile[row][c4 + 2] = v.z; tile[row][c4 + 3] = v.w;
    }
    __syncthreads();
    #pragma unroll
    for (int i = 0; i < 4; i++) {
        const int idx = t + (i << 8);
        const int d = idx >> 4, sc = (idx & 15) << 2;
        uint16_t hh[4], ll[4];
        #pragma unroll
        for (int k = 0; k < 4; k++) {
            const float f = tile[sc + k][d];
            __nv_bfloat16 hb = __float2bfloat16(f);
            const float lf = f - __bfloat162float(hb);
            __nv_bfloat16 lb = __float2bfloat16(lf);
            hh[k] = *(uint16_t*)&hb; ll[k] = *(uint16_t*)&lb;
        }
        uint2 hv = make_uint2((uint32_t)hh[0] | ((uint32_t)hh[1] << 16),
                              (uint32_t)hh[2] | ((uint32_t)hh[3] << 16));
        uint2 lv = make_uint2((uint32_t)ll[0] | ((uint32_t)ll[1] << 16),
                              (uint32_t)ll[2] | ((uint32_t)ll[3] << 16));
        *(uint2*)(vh + (size_t)(bh * 64 + d) * Ss + s0 + sc) = hv;
        *(uint2*)(vl + (size_t)(bh * 64 + d) * Ss + s0 + sc) = lv;
    }
}

// ---------------- flash attention on tensor cores (split-bf16) --------------
#define AT_SMEM 98304

#define S_TERM(AF, KB)                                                          \
    _Pragma("unroll")                                                           \
    for (int ks = 0; ks < 4; ks++) {                                            \
        uint32_t bfr[4][4];                                                     \
        _Pragma("unroll")                                                       \
        for (int n4 = 0; n4 < 4; n4++)                                          \
            ldsm4(bfr[n4], (KB) + sw128(((nrow + n4 * 16) << 7) + ks * 32 + bcb)); \
        _Pragma("unroll")                                                       \
        for (int nt = 0; nt < 8; nt++)                                          \
            mma16816(sA[nt], AF[ks],                                            \
                     bfr[nt >> 1][(nt & 1) * 2], bfr[nt >> 1][(nt & 1) * 2 + 1]); \
    }

__global__ void __launch_bounds__(256)
flash_attn(const __nv_bfloat16* __restrict__ qkh, const __nv_bfloat16* __restrict__ qkl,
           const __nv_bfloat16* __restrict__ vth, const __nv_bfloat16* __restrict__ vtl)
{
    extern __shared__ char sm[];
    const uint32_t sb = smem_u32(sm);
    const int t = threadIdx.x, lane = t & 31, w = t >> 5;
    const int bh = blockIdx.y, b = bh >> 3, h = bh & 7;
    const int q0 = blockIdx.x << 7;
    const uint32_t Qh = sb, Ql = sb + 16384;

    {
        const char* srch = (const char*)(qkh + (size_t)(b * Ss + q0) * 1024 + h * 64);
        const char* srcl = (const char*)(qkl + (size_t)(b * Ss + q0) * 1024 + h * 64);
        #pragma unroll
        for (int i = 0; i < 4; i++) {
            const int idx = t + (i << 8);
            const int row = idx >> 3, ch = (idx & 7) << 4;
            const uint32_t off = sw128((row << 7) | ch);
            cp16(Qh + off, srch + (size_t)row * 2048 + ch);
            cp16(Ql + off, srcl + (size_t)row * 2048 + ch);
        }
        asm volatile("cp.async.commit_group;" ::: "memory");
    }

    auto load_kv = [&](int kt, int buf) {
        const uint32_t bb = sb + 32768 + buf * 32768;
        const char* kh = (const char*)(qkh + (size_t)(b * Ss + kt * 64) * 1024 + 512 + h * 64);
        const char* kl = (const char*)(qkl + (size_t)(b * Ss + kt * 64) * 1024 + 512 + h * 64);
        const char* vh = (const char*)(vth + (size_t)(bh * 64) * Ss + kt * 64);
        const char* vl = (const char*)(vtl + (size_t)(bh * 64) * Ss + kt * 64);
        #pragma unroll
        for (int i = 0; i < 2; i++) {
            const int idx = t + (i << 8);
            const int row = idx >> 3, ch = (idx & 7) << 4;
            const uint32_t off = sw128((row << 7) | ch);
            cp16(bb + off,         kh + (size_t)row * 2048 + ch);
            cp16(bb + 8192 + off,  kl + (size_t)row * 2048 + ch);
            cp16(bb + 16384 + off, vh + (size_t)row * 2048 + ch);
            cp16(bb + 24576 + off, vl + (size_t)row * 2048 + ch);
        }
        asm volatile("cp.async.commit_group;" ::: "memory");
    };
    load_kv(0, 0);
    load_kv(1, 1);

    asm volatile("cp.async.wait_group 2;" ::: "memory");
    __syncthreads();

    const int arow = (w << 4) + (lane & 15);
    const int acb  = (lane >> 4) << 4;
    uint32_t qh[4][4], ql[4][4];
    #pragma unroll
    for (int ks = 0; ks < 4; ks++) {
        ldsm4(qh[ks], Qh + sw128((arow << 7) + ks * 32 + acb));
        ldsm4(ql[ks], Ql + sw128((arow << 7) + ks * 32 + acb));
    }

    const int nrow = ((lane >> 4) & 1) * 8 + (lane & 7);
    const int bcb  = ((lane >> 3) & 1) << 4;

    float o[8][4] = {};
    float m0 = -INFINITY, m1 = -INFINITY, l0 = 0.f, l1 = 0.f;

    for (int kt = 0; kt < 16; kt++) {
        const int buf = kt & 1;
        if (kt + 1 < 16) asm volatile("cp.async.wait_group 1;" ::: "memory");
        else             asm volatile("cp.async.wait_group 0;" ::: "memory");
        __syncthreads();
        const uint32_t Kh = sb + 32768 + buf * 32768;
        const uint32_t Kl = Kh + 8192, Vh = Kh + 16384, Vl = Kh + 24576;

        float sA[8][4] = {};
        S_TERM(qh, Kh)
        S_TERM(qh, Kl)
        S_TERM(ql, Kh)

        float rm0 = -INFINITY, rm1 = -INFINITY;
        #pragma unroll
        for (int nt = 0; nt < 8; nt++) {
            #pragma unroll
            for (int j = 0; j < 4; j++) sA[nt][j] *= 0.125f;
            rm0 = fmaxf(rm0, fmaxf(sA[nt][0], sA[nt][1]));
            rm1 = fmaxf(rm1, fmaxf(sA[nt][2], sA[nt][3]));
        }
        rm0 = fmaxf(rm0, __shfl_xor_sync(0xffffffffu, rm0, 1));
        rm0 = fmaxf(rm0, __shfl_xor_sync(0xffffffffu, rm0, 2));
        rm1 = fmaxf(rm1, __shfl_xor_sync(0xffffffffu, rm1, 1));
        rm1 = fmaxf(rm1, __shfl_xor_sync(0xffffffffu, rm1, 2));
        const float mn0 = fmaxf(m0, rm0), mn1 = fmaxf(m1, rm1);
        const float sc0 = __expf(m0 - mn0), sc1 = __expf(m1 - mn1);
        m0 = mn0; m1 = mn1;

        float ps0 = 0.f, ps1 = 0.f;
        uint32_t phi[4][4], plo[4][4];
        #pragma unroll
        for (int j = 0; j < 4; j++) {
            float p[2][4];
            #pragma unroll
            for (int e = 0; e < 2; e++) {
                p[e][0] = __expf(sA[2 * j + e][0] - mn0);
                p[e][1] = __expf(sA[2 * j + e][1] - mn0);
                p[e][2] = __expf(sA[2 * j + e][2] - mn1);
                p[e][3] = __expf(sA[2 * j + e][3] - mn1);
                ps0 += p[e][0] + p[e][1];
                ps1 += p[e][2] + p[e][3];
            }
            float r0, r1;
            phi[j][0] = pack_bf2(p[0][0], p[0][1], r0, r1); plo[j][0] = pack_bf2n(r0, r1);
            phi[j][1] = pack_bf2(p[0][2], p[0][3], r0, r1); plo[j][1] = pack_bf2n(r0, r1);
            phi[j][2] = pack_bf2(p[1][0], p[1][1], r0, r1); plo[j][2] = pack_bf2n(r0, r1);
            phi[j][3] = pack_bf2(p[1][2], p[1][3], r0, r1); plo[j][3] = pack_bf2n(r0, r1);
        }
        l0 = l0 * sc0 + ps0;
        l1 = l1 * sc1 + ps1;
        #pragma unroll
        for (int nt = 0; nt < 8; nt++) {
            o[nt][0] *= sc0; o[nt][1] *= sc0;
            o[nt][2] *= sc1; o[nt][3] *= sc1;
        }

        #pragma unroll
        for (int ks = 0; ks < 4; ks++) {
            uint32_t bv[4][4];
            #pragma unroll
            for (int n4 = 0; n4 < 4; n4++)
                ldsm4(bv[n4], Vh + sw128(((nrow + n4 * 16) << 7) + ks * 32 + bcb));
            #pragma unroll
            for (int nt = 0; nt < 8; nt++) {
                mma16816(o[nt], phi[ks], bv[nt >> 1][(nt & 1) * 2], bv[nt >> 1][(nt & 1) * 2 + 1]);
                mma16816(o[nt], plo[ks], bv[nt >> 1][(nt & 1) * 2], bv[nt >> 1][(nt & 1) * 2 + 1]);
            }
            #pragma unroll
            for (int n4 = 0; n4 < 4; n4++)
                ldsm4(bv[n4], Vl + sw128(((nrow + n4 * 16) << 7) + ks * 32 + bcb));
            #pragma unroll
            for (int nt = 0; nt < 8; nt++)
                mma16816(o[nt], phi[ks], bv[nt >> 1][(nt & 1) * 2], bv[nt >> 1][(nt & 1) * 2 + 1]);
        }
        __syncthreads();
        if (kt + 2 < 16) load_kv(kt + 2, buf);
    }

    // epilogue: write split [hi|hi|lo] A2 rows directly
    l0 += __shfl_xor_sync(0xffffffffu, l0, 1);
    l0 += __shfl_xor_sync(0xffffffffu, l0, 2);
    l1 += __shfl_xor_sync(0xffffffffu, l1, 1);
    l1 += __shfl_xor_sync(0xffffffffu, l1, 2);
    const float i0 = 1.f / l0, i1 = 1.f / l1;
    const int r = lane >> 2, c2 = (lane & 3) << 1;
    const int row0 = b * Ss + q0 + (w << 4) + r;
    __nv_bfloat16* a2a = g_A2 + (size_t)row0 * 3072;
    __nv_bfloat16* a2b = g_A2 + (size_t)(row0 + 8) * 3072;
    #pragma unroll
    for (int nt = 0; nt < 8; nt++) {
        const int col = 512 + h * 64 + nt * 8 + c2;
        float r0, r1;
        uint32_t hi = pack_bf2(o[nt][0] * i0, o[nt][1] * i0, r0, r1);
        uint32_t lo = pack_bf2n(r0, r1);
        *(uint32_t*)(a2a + col)        = hi;
        *(uint32_t*)(a2a + 1024 + col) = hi;
        *(uint32_t*)(a2a + 2048 + col) = lo;
        hi = pack_bf2(o[nt][2] * i1, o[nt][3] * i1, r0, r1);
        lo = pack_bf2n(r0, r1);
        *(uint32_t*)(a2b + col)        = hi;
        *(uint32_t*)(a2b + 1024 + col) = hi;
        *(uint32_t*)(a2b + 2048 + col) = lo;
    }
}

// ---------------- fp32 SIMT GEMM for Wc (double-buffered) --------------------
__global__ void __launch_bounds__(256)
wc_gemm(const float* __restrict__ Wf, const float* __restrict__ Wl_out,
        const float* __restrict__ Wg_out, float* __restrict__ Wc)
{
    __shared__ float As[2][16][68];
    __shared__ float Bs[2][16][68];
    const int g = blockIdx.z;
    const float* A = Wf + (g ? Ee : 0);
    const float* W = g ? Wg_out : Wl_out;
    float* C = Wc + (g ? Ee : 0);
    const int t = threadIdx.x, tx = t & 15, ty = t >> 4;
    const int m0 = blockIdx.y * 64, n0 = blockIdx.x * 64;
    const int lr = t >> 2, lk = (t & 3) << 2;
    const int bkk = t >> 4, bcc = (t & 15) << 2;
    float acc[4][4] = {};

    float4 va = *(const float4*)(A + (size_t)(m0 + lr) * (2 * Ee) + lk);
    float4 vb = *(const float4*)(W + (size_t)bkk * Ee + n0 + bcc);
    int buf = 0;
    for (int k0 = 0; k0 < Ee; k0 += 16) {
        As[buf][lk + 0][lr] = va.x; As[buf][lk + 1][lr] = va.y;
        As[buf][lk + 2][lr] = va.z; As[buf][lk + 3][lr] = va.w;
        *(float4*)&Bs[buf][bkk][bcc] = vb;
        __syncthreads();
        if (k0 + 16 < Ee) {
            va = *(const float4*)(A + (size_t)(m0 + lr) * (2 * Ee) + k0 + 16 + lk);
            vb = *(const float4*)(W + (size_t)(k0 + 16 + bkk) * Ee + n0 + bcc);
        }
        #pragma unroll
        for (int kk = 0; kk < 16; kk++) {
            float4 a = *(const float4*)&As[buf][kk][ty << 2];
            float4 b = *(const float4*)&Bs[buf][kk][tx << 2];
            float av[4] = {a.x, a.y, a.z, a.w};
            float bv[4] = {b.x, b.y, b.z, b.w};
            #pragma unroll
            for (int i = 0; i < 4; i++)
                #pragma unroll
                for (int j = 0; j < 4; j++)
                    acc[i][j] = fmaf(av[i], bv[j], acc[i][j]);
        }
        buf ^= 1;
    }
    #pragma unroll
    for (int i = 0; i < 4; i++)
        *(float4*)(C + (size_t)(m0 + (ty << 2) + i) * (2 * Ee) + n0 + (tx << 2)) =
            make_float4(acc[i][0], acc[i][1], acc[i][2], acc[i][3]);
}

// ---------------- combined bias (parallel) ------------------------------------
__global__ void __launch_bounds__(128)
bias_combine_kernel(const float* __restrict__ Wf,
                    const float* __restrict__ bl,
                    const float* __restrict__ bg,
                    const float* __restrict__ bf)
{
    const int o = blockIdx.x;
    const int t = threadIdx.x;
    const float* row = Wf + (size_t)o * (2 * Ee);
    float acc = 0.f;
    for (int j = t; j < Ee; j += 128)
        acc += row[j] * bl[j] + row[Ee + j] * bg[j];
    #pragma unroll
    for (int off = 16; off; off >>= 1)
        acc += __shfl_xor_sync(0xffffffffu, acc, off);
    __shared__ float ws[4];
    if ((t & 31) == 0) ws[t >> 5] = acc;
    __syncthreads();
    if (t == 0) g_bc[o] = ws[0] + ws[1] + ws[2] + ws[3] + bf[o];
}

// ---------------- local (banded) attention -> A2 splits ----------------------
__global__ void __launch_bounds__(256)
local_attn_kernel(const float* __restrict__ qkv)
{
    const int warp = (blockIdx.x * blockDim.x + threadIdx.x) >> 5;
    const int lane = threadIdx.x & 31;
    const int q  = warp & (Ss - 1);
    const int bh = warp >> 10;
    const int b  = bh >> 3, h = bh & 7;

    const float* base = qkv + (size_t)(b * Ss) * QKVN + h * DHd;
    const float* qrow = base + (size_t)q * QKVN;
    const float q0 = qrow[lane], q1 = qrow[lane + 32];

    float s[7];
    float mmax = -1e30f;
    #pragma unroll
    for (int jj = 0; jj < 7; jj++) {
        const int j = q - LOCALW + jj;
        const bool valid = (j >= 0) && (j < Ss);
        float d = 0.f;
        if (valid) {
            const float* krow = base + (size_t)j * QKVN + Ee;
            d = q0 * krow[lane] + q1 * krow[lane + 32];
        }
        #pragma unroll
        for (int off = 16; off; off >>= 1)
            d += __shfl_xor_sync(0xffffffffu, d, off);
        d = valid ? d * 0.125f : -1e30f;
        s[jj] = d;
        mmax = fmaxf(mmax, d);
    }
    float sum = 0.f;
    #pragma unroll
    for (int jj = 0; jj < 7; jj++) { s[jj] = __expf(s[jj] - mmax); sum += s[jj]; }
    const float inv = 1.f / sum;
    float o0 = 0.f, o1 = 0.f;
    #pragma unroll
    for (int jj = 0; jj < 7; jj++) {
        const int j = q - LOCALW + jj;
        if (j >= 0 && j < Ss) {
            const float* vrow = base + (size_t)j * QKVN + 2 * Ee;
            o0 = fmaf(s[jj], vrow[lane],      o0);
            o1 = fmaf(s[jj], vrow[lane + 32], o1);
        }
    }
    const float v0 = o0 * inv, v1 = o1 * inv;
    const float p0 = __shfl_down_sync(0xffffffffu, v0, 1);
    const float p1 = __shfl_down_sync(0xffffffffu, v1, 1);
    if (!(lane & 1)) {
        __nv_bfloat16* a2 = g_A2 + (size_t)(b * Ss + q) * 3072;
        const int c0 = h * DHd + lane;          // even, cols [0,512)
        float r0, r1;
        uint32_t hi = pack_bf2(v0, p0, r0, r1);
        uint32_t lo = pack_bf2n(r0, r1);
        *(uint32_t*)(a2 + c0)        = hi;
        *(uint32_t*)(a2 + 1024 + c0) = hi;
        *(uint32_t*)(a2 + 2048 + c0) = lo;
        hi = pack_bf2(v1, p1, r0, r1);
        lo = pack_bf2n(r0, r1);
        *(uint32_t*)(a2 + c0 + 32)        = hi;
        *(uint32_t*)(a2 + 1024 + c0 + 32) = hi;
        *(uint32_t*)(a2 + 2048 + c0 + 32) = lo;
    }
}

// ---------------- launcher -----------------------------------------------------
extern "C" void kernel_launch(void* const* d_in, const int* in_sizes, int n_in,
                              void* d_out, int out_size)
{
    (void)in_sizes; (void)n_in; (void)out_size;
    const float* x      = (const float*)d_in[0];
    const float* Wl_in  = (const float*)d_in[1];
    const float* bl_in  = (const float*)d_in[2];
    const float* Wl_out = (const float*)d_in[3];
    const float* bl_out = (const float*)d_in[4];
    const float* Wg_in  = (const float*)d_in[5];
    const float* bg_in  = (const float*)d_in[6];
    const float* Wg_out = (const float*)d_in[7];
    const float* bg_out = (const float*)d_in[8];
    const float* Wf     = (const float*)d_in[9];
    const float* bf     = (const float*)d_in[10];
    float* out = (float*)d_out;

    float *qkv_l, *vg, *Wc, *bc;
    __nv_bfloat16 *A1, *B1l, *B1g, *A2, *B2, *qkh, *qkl, *vth, *vtl;
    cudaGetSymbolAddress((void**)&qkv_l, g_qkv_l);
    cudaGetSymbolAddress((void**)&vg,    g_vg);
    cudaGetSymbolAddress((void**)&Wc,    g_Wc);
    cudaGetSymbolAddress((void**)&bc,    g_bc);
    cudaGetSymbolAddress((void**)&A1,    g_A1);
    cudaGetSymbolAddress((void**)&B1l,   g_B1l);
    cudaGetSymbolAddress((void**)&B1g,   g_B1g);
    cudaGetSymbolAddress((void**)&A2,    g_A2);
    cudaGetSymbolAddress((void**)&B2,    g_B2);
    cudaGetSymbolAddress((void**)&qkh,   g_qk_h);
    cudaGetSymbolAddress((void**)&qkl,   g_qk_l);
    cudaGetSymbolAddress((void**)&vth,   g_vt_h);
    cudaGetSymbolAddress((void**)&vtl,   g_vt_l);

    cudaFuncSetAttribute(mma_gemm<true>,
                         cudaFuncAttributeMaxDynamicSharedMemorySize, MMA_SMEM);
    cudaFuncSetAttribute(qkv_fused,
                         cudaFuncAttributeMaxDynamicSharedMemorySize, MMA_SMEM);
    cudaFuncSetAttribute(flash_attn,
                         cudaFuncAttributeMaxDynamicSharedMemorySize, AT_SMEM);

    // 1) splits of x and input-proj weights
    split_ab<0><<<(Mm * Ee) / 4 / 256, 256>>>(x, A1, 9);
    split_ab<1><<<(QKVN * Ee) / 4 / 256, 256>>>(Wl_in, B1l, 9);
    split_ab<1><<<(QKVN * Ee) / 4 / 256, 256>>>(Wg_in, B1g, 9);

    // 2) combined epilogue weights + bias, then split
    wc_gemm<<<dim3(8, 8, 2), 256>>>(Wf, Wl_out, Wg_out, Wc);
    bias_combine_kernel<<<Ee, 128>>>(Wf, bl_out, bg_out, bf);
    split_ab<1><<<(Ee * 2 * Ee) / 4 / 256, 256>>>(Wc, B2, 10);

    // 3) fused QKV projections (both blocks; split epilogues)
    qkv_fused<<<dim3(QKVN / 128, Mm / 128, 2), 256, MMA_SMEM>>>(
        A1, B1l, B1g, bl_in, bg_in);

    // 4) local attention -> A2
    local_attn_kernel<<<(Bb * Hh * Ss) / 8, 256>>>(qkv_l);

    // 5) V transpose-split, flash attention -> A2
    vt_split<<<dim3(Ss / 64, Bb * Hh), 256>>>(vg, vth, vtl);
    flash_attn<<<dim3(Ss / 128, Bb * Hh), 256, AT_SMEM>>>(qkh, qkl, vth, vtl);

    // 6) final fused projection + ReLU
    mma_gemm<true><<<dim3(Ee / 128, Mm / 128), 256, MMA_SMEM>>>(
        A2, B2, bc, out, 3 * 2 * Ee, Ee);
}